// round 1
// baseline (speedup 1.0000x reference)
#include <cuda_runtime.h>
#include <math.h>

// ---------------------------------------------------------------------------
// SNN_Model: 3-step spiking net with Hebbian fast weights, fp32 SIMT GEMMs.
//
// Restructuring vs reference:
//   C1 = x @ (W1^T . mask0) computed once (x constant across steps).
//   state1_s = d_s*C1 + d_s*alpha1*(x @ hebbM1)
//   state2_s = d_s*(spike1 @ (W2m + alpha2*hebbM2))
//   hebbM    = hebb .(1-mask) stored directly; mask folded into update epilogue.
//   Final-step hebb updates skipped (never consumed).
// All mem/spike/post elementwise work fused into GEMM epilogues.
// ---------------------------------------------------------------------------

static constexpr int B_   = 8192;
static constexpr int IN_  = 784;
static constexpr int H1_  = 1024;
static constexpr int H2_  = 1024;
static constexpr int OUT_ = 10;

// Scratch (device globals; runtime allocation is forbidden)
__device__ float g_Wm1[IN_ * H1_];          // fc1^T . mask0
__device__ float g_Wm2[H1_ * H2_];          // fc2^T . mask1
__device__ float g_Wm3[H2_ * OUT_];         // fc3^T . mask2
__device__ float g_fw2[H1_ * H2_];          // Wm2 + alpha2*hebbM2
__device__ float g_C1 [(size_t)B_ * H1_];
__device__ float g_m1 [(size_t)B_ * H1_];
__device__ float g_s1 [(size_t)B_ * H1_];
__device__ float g_p1 [(size_t)B_ * H1_];
__device__ float g_m2 [(size_t)B_ * H2_];
__device__ float g_s2 [(size_t)B_ * H2_];
__device__ float g_p2 [(size_t)B_ * H2_];
__device__ float g_hb1[IN_ * H1_];          // hebb1 .(1-mask0)
__device__ float g_hb2[H1_ * H2_];          // hebb2 .(1-mask1)

// ---------------------------------------------------------------------------
// Elementwise prep kernels
// ---------------------------------------------------------------------------

// out[k*N + n] = W[n*K + k] * mask[k*N + n]   (W is (N,K) row-major)
__global__ void prep_wt(const float* __restrict__ W, const float* __restrict__ mask,
                        float* __restrict__ out, int Kdim, int Ndim) {
    int idx = blockIdx.x * blockDim.x + threadIdx.x;
    int total = Kdim * Ndim;
    if (idx < total) {
        int k = idx / Ndim;
        int n = idx - k * Ndim;
        out[idx] = W[(size_t)n * Kdim + k] * mask[idx];
    }
}

__global__ void zero_hebb() {
    int idx = blockIdx.x * blockDim.x + threadIdx.x;
    if (idx < IN_ * H1_) g_hb1[idx] = 0.0f;
    if (idx < H1_ * H2_) g_hb2[idx] = 0.0f;
}

// fw2 = Wm2 + alpha2 * hebbM2
__global__ void fw2_add(const float* __restrict__ alpha2) {
    int idx = blockIdx.x * blockDim.x + threadIdx.x;
    if (idx < H1_ * H2_) g_fw2[idx] = fmaf(alpha2[0], g_hb2[idx], g_Wm2[idx]);
}

// ---------------------------------------------------------------------------
// Forward SGEMM: C(M=8192 x N=1024) = A(M x K) @ Bw(K x N), fused SNN epilogue.
// BM=BN=128, BK=8, 256 threads, 8x8 per thread.
// EP: 1 = store acc to C1 AND run step-0 layer-1 epilogue (state = acc)
//     2 = layer-1 steps 1/2: state = d*(C1 + alpha*acc)
//     3 = layer-2:           state = d*acc
// ---------------------------------------------------------------------------
template <int EP, bool POST, bool FIRST>
__global__ void __launch_bounds__(256)
sgemm_fwd(const float* __restrict__ A, const float* __restrict__ Bw, int K,
          float dscale,
          const float* __restrict__ alpha,   // device scalar (EP==2)
          const float* __restrict__ eta,     // per-column
          const float* __restrict__ C1in,    // EP==2
          float* __restrict__ C1out,         // EP==1
          float* __restrict__ memA, float* __restrict__ spkA,
          float* __restrict__ postA) {
    constexpr int BM = 128, BN = 128, BK = 8, N = 1024;
    __shared__ float As[BK][BM];
    __shared__ float Bs[BK][BN];

    const int tid = threadIdx.x;
    const int bm = blockIdx.y, bn = blockIdx.x;

    const float* Ablk = A + (size_t)bm * BM * K;
    const float* Bblk = Bw + bn * BN;

    const int arow = tid >> 1;           // 0..127
    const int acol = (tid & 1) * 4;      // 0 or 4
    const int brow = tid >> 5;           // 0..7
    const int bcol = (tid & 31) * 4;     // 0..124

    const int tm0 = (tid >> 4) * 8;
    const int tn0 = (tid & 15) * 8;

    float acc[8][8];
#pragma unroll
    for (int i = 0; i < 8; i++)
#pragma unroll
        for (int j = 0; j < 8; j++) acc[i][j] = 0.0f;

    for (int k0 = 0; k0 < K; k0 += BK) {
        float4 av = *reinterpret_cast<const float4*>(Ablk + (size_t)arow * K + k0 + acol);
        float4 bv = *reinterpret_cast<const float4*>(Bblk + (size_t)(k0 + brow) * N + bcol);
        As[acol + 0][arow] = av.x;
        As[acol + 1][arow] = av.y;
        As[acol + 2][arow] = av.z;
        As[acol + 3][arow] = av.w;
        *reinterpret_cast<float4*>(&Bs[brow][bcol]) = bv;
        __syncthreads();
#pragma unroll
        for (int kk = 0; kk < BK; ++kk) {
            float4 a0 = *reinterpret_cast<const float4*>(&As[kk][tm0]);
            float4 a1 = *reinterpret_cast<const float4*>(&As[kk][tm0 + 4]);
            float4 b0 = *reinterpret_cast<const float4*>(&Bs[kk][tn0]);
            float4 b1 = *reinterpret_cast<const float4*>(&Bs[kk][tn0 + 4]);
            float ra[8] = {a0.x, a0.y, a0.z, a0.w, a1.x, a1.y, a1.z, a1.w};
            float rb[8] = {b0.x, b0.y, b0.z, b0.w, b1.x, b1.y, b1.z, b1.w};
#pragma unroll
            for (int i = 0; i < 8; i++)
#pragma unroll
                for (int j = 0; j < 8; j++)
                    acc[i][j] = fmaf(ra[i], rb[j], acc[i][j]);
        }
        __syncthreads();
    }

    // ---- fused epilogue ----
    const float alphaV = (EP == 2) ? alpha[0] : 0.0f;
    const int ncol0 = bn * BN + tn0;
    float et[8];
#pragma unroll
    for (int jj = 0; jj < 8; jj += 4) {
        float4 ev = *reinterpret_cast<const float4*>(&eta[ncol0 + jj]);
        et[jj + 0] = ev.x; et[jj + 1] = ev.y; et[jj + 2] = ev.z; et[jj + 3] = ev.w;
    }

#pragma unroll
    for (int i = 0; i < 8; i++) {
        size_t base = (size_t)(bm * BM + tm0 + i) * N + ncol0;
#pragma unroll
        for (int jj = 0; jj < 8; jj += 4) {
            float st[4], mmv[4], spv[4], pov[4];
            float c1v[4], omv[4], osv[4];
            if (EP == 2) {
                float4 cv = *reinterpret_cast<const float4*>(C1in + base + jj);
                c1v[0] = cv.x; c1v[1] = cv.y; c1v[2] = cv.z; c1v[3] = cv.w;
            }
            if (!FIRST) {
                float4 mv = *reinterpret_cast<const float4*>(memA + base + jj);
                float4 sv = *reinterpret_cast<const float4*>(spkA + base + jj);
                omv[0] = mv.x; omv[1] = mv.y; omv[2] = mv.z; omv[3] = mv.w;
                osv[0] = sv.x; osv[1] = sv.y; osv[2] = sv.z; osv[3] = sv.w;
            }
#pragma unroll
            for (int j = 0; j < 4; j++) {
                float a = acc[i][jj + j];
                if (EP == 1)      st[j] = a;
                else if (EP == 2) st[j] = dscale * (c1v[j] + alphaV * a);
                else              st[j] = dscale * a;
                float mem = FIRST ? st[j]
                                  : (omv[j] - osv[j] * 0.5f) * 0.8f + st[j];
                mmv[j] = mem;
                spv[j] = ((mem - 0.5f) > 0.0f) ? 1.0f : 0.0f;
                if (POST) pov[j] = tanhf(2.0f * mem - et[jj + j]);
            }
            if (EP == 1)
                *reinterpret_cast<float4*>(C1out + base + jj) =
                    make_float4(acc[i][jj], acc[i][jj + 1], acc[i][jj + 2], acc[i][jj + 3]);
            *reinterpret_cast<float4*>(memA + base + jj) =
                make_float4(mmv[0], mmv[1], mmv[2], mmv[3]);
            *reinterpret_cast<float4*>(spkA + base + jj) =
                make_float4(spv[0], spv[1], spv[2], spv[3]);
            if (POST)
                *reinterpret_cast<float4*>(postA + base + jj) =
                    make_float4(pov[0], pov[1], pov[2], pov[3]);
        }
    }
}

// ---------------------------------------------------------------------------
// Hebb SGEMM: Hb(M x N=1024) = 0.8*Hb + (1-mask)*beta[i]*(d/B) * (A^T @ P)
// A is (K=8192 x M), P is (K x N), both K-major. BM=BN=64, BK=16, 4x4/thread.
// ---------------------------------------------------------------------------
__global__ void __launch_bounds__(256)
sgemm_hebb(const float* __restrict__ A, const float* __restrict__ P,
           float* __restrict__ Hb, const float* __restrict__ mask,
           const float* __restrict__ beta, int M, float dscale) {
    constexpr int BM = 64, BN = 64, BK = 16, N = 1024, K = 8192;
    __shared__ float As[BK][BM];
    __shared__ float Ps[BK][BN];

    const int tid = threadIdx.x;
    const int m0 = blockIdx.y * BM, n0 = blockIdx.x * BN;

    const int lrow = tid >> 4;          // k within tile 0..15
    const int lcol = (tid & 15) * 4;    // 0..60

    const int tm0 = (tid >> 4) * 4;
    const int tn0 = (tid & 15) * 4;

    float acc[4][4];
#pragma unroll
    for (int i = 0; i < 4; i++)
#pragma unroll
        for (int j = 0; j < 4; j++) acc[i][j] = 0.0f;

    const int gm = m0 + lcol;
    const bool aok = (gm < M);

    for (int k0 = 0; k0 < K; k0 += BK) {
        float4 av = aok ? *reinterpret_cast<const float4*>(A + (size_t)(k0 + lrow) * M + gm)
                        : make_float4(0.f, 0.f, 0.f, 0.f);
        float4 pv = *reinterpret_cast<const float4*>(P + (size_t)(k0 + lrow) * N + n0 + lcol);
        *reinterpret_cast<float4*>(&As[lrow][lcol]) = av;
        *reinterpret_cast<float4*>(&Ps[lrow][lcol]) = pv;
        __syncthreads();
#pragma unroll
        for (int kk = 0; kk < BK; ++kk) {
            float4 a = *reinterpret_cast<const float4*>(&As[kk][tm0]);
            float4 p = *reinterpret_cast<const float4*>(&Ps[kk][tn0]);
            float ra[4] = {a.x, a.y, a.z, a.w};
            float rp[4] = {p.x, p.y, p.z, p.w};
#pragma unroll
            for (int i = 0; i < 4; i++)
#pragma unroll
                for (int j = 0; j < 4; j++)
                    acc[i][j] = fmaf(ra[i], rp[j], acc[i][j]);
        }
        __syncthreads();
    }

    const float inv = dscale / 8192.0f;
#pragma unroll
    for (int i = 0; i < 4; i++) {
        int ig = m0 + tm0 + i;
        if (ig >= M) continue;
        float bscale = beta[ig] * inv;
        size_t base = (size_t)ig * N + n0 + tn0;
#pragma unroll
        for (int j = 0; j < 4; j++) {
            size_t idx = base + j;
            Hb[idx] = 0.8f * Hb[idx] + (1.0f - mask[idx]) * bscale * acc[i][j];
        }
    }
}

// ---------------------------------------------------------------------------
// Output GEMM: out(B x 10) = h2_mem(B x 1024) @ Wm3(1024 x 10)
// One warp per batch row; Wm3 staged in shared memory.
// ---------------------------------------------------------------------------
__global__ void __launch_bounds__(256)
out_gemm(const float* __restrict__ m2, const float* __restrict__ Wm3,
         float* __restrict__ out) {
    __shared__ float sW[H2_ * OUT_];   // 40 KB
    const int tid = threadIdx.x;
    for (int i = tid; i < H2_ * OUT_; i += blockDim.x) sW[i] = Wm3[i];
    __syncthreads();

    const int warp = tid >> 5, lane = tid & 31;
    const int b = blockIdx.x * 8 + warp;
    const float* row = m2 + (size_t)b * H2_;

    float acc[OUT_];
#pragma unroll
    for (int j = 0; j < OUT_; j++) acc[j] = 0.0f;

    for (int k = lane; k < H2_; k += 32) {
        float v = row[k];
#pragma unroll
        for (int j = 0; j < OUT_; j++) acc[j] = fmaf(v, sW[k * OUT_ + j], acc[j]);
    }
#pragma unroll
    for (int j = 0; j < OUT_; j++) {
        float s = acc[j];
#pragma unroll
        for (int o = 16; o > 0; o >>= 1) s += __shfl_xor_sync(0xffffffffu, s, o);
        if (lane == 0) out[(size_t)b * OUT_ + j] = s;
    }
}

// ---------------------------------------------------------------------------
extern "C" void kernel_launch(void* const* d_in, const int* in_sizes, int n_in,
                              void* d_out, int out_size) {
    const float* x      = (const float*)d_in[0];
    const float* mask0  = (const float*)d_in[1];
    const float* mask1  = (const float*)d_in[2];
    const float* mask2  = (const float*)d_in[3];
    const float* fc1    = (const float*)d_in[4];
    const float* fc2    = (const float*)d_in[5];
    const float* fc3    = (const float*)d_in[6];
    const float* alpha1 = (const float*)d_in[7];
    const float* alpha2 = (const float*)d_in[8];
    const float* beta1  = (const float*)d_in[9];
    const float* beta2  = (const float*)d_in[10];
    const float* eta1   = (const float*)d_in[11];
    const float* eta2   = (const float*)d_in[12];
    float* out = (float*)d_out;

    float *Wm1, *Wm2, *Wm3, *C1, *m1, *s1, *p1, *m2, *s2, *p2, *hb1, *hb2, *fw2;
    cudaGetSymbolAddress((void**)&Wm1, g_Wm1);
    cudaGetSymbolAddress((void**)&Wm2, g_Wm2);
    cudaGetSymbolAddress((void**)&Wm3, g_Wm3);
    cudaGetSymbolAddress((void**)&fw2, g_fw2);
    cudaGetSymbolAddress((void**)&C1,  g_C1);
    cudaGetSymbolAddress((void**)&m1,  g_m1);
    cudaGetSymbolAddress((void**)&s1,  g_s1);
    cudaGetSymbolAddress((void**)&p1,  g_p1);
    cudaGetSymbolAddress((void**)&m2,  g_m2);
    cudaGetSymbolAddress((void**)&s2,  g_s2);
    cudaGetSymbolAddress((void**)&p2,  g_p2);
    cudaGetSymbolAddress((void**)&hb1, g_hb1);
    cudaGetSymbolAddress((void**)&hb2, g_hb2);

    const float d0 = 1.0f;
    const float d1 = 0.98019867330675525f;   // float32(exp(-1/50))
    const float d2 = 0.96078943915232320f;   // float32(exp(-2/50))

    // ---- prep ----
    prep_wt<<<(IN_ * H1_ + 255) / 256, 256>>>(fc1, mask0, Wm1, IN_, H1_);
    prep_wt<<<(H1_ * H2_ + 255) / 256, 256>>>(fc2, mask1, Wm2, H1_, H2_);
    prep_wt<<<(H2_ * OUT_ + 255) / 256, 256>>>(fc3, mask2, Wm3, H2_, OUT_);
    zero_hebb<<<(H1_ * H2_ + 255) / 256, 256>>>();

    dim3 gF(H1_ / 128, B_ / 128);             // (8, 64)
    dim3 gH1(H1_ / 64, (IN_ + 63) / 64);      // (16, 13)
    dim3 gH2(H2_ / 64, H1_ / 64);             // (16, 16)

    // ---- step 0 (d=1, hebb=0) ----
    sgemm_fwd<1, true, true><<<gF, 256>>>(x, Wm1, IN_, d0, nullptr, eta1,
                                          nullptr, C1, m1, s1, p1);
    sgemm_hebb<<<gH1, 256>>>(x, p1, hb1, mask0, beta1, IN_, d0);
    sgemm_fwd<3, true, true><<<gF, 256>>>(s1, Wm2, H1_, d0, nullptr, eta2,
                                          nullptr, nullptr, m2, s2, p2);
    sgemm_hebb<<<gH2, 256>>>(s1, p2, hb2, mask1, beta2, H1_, d0);

    // ---- step 1 ----
    sgemm_fwd<2, true, false><<<gF, 256>>>(x, hb1, IN_, d1, alpha1, eta1,
                                           C1, nullptr, m1, s1, p1);
    sgemm_hebb<<<gH1, 256>>>(x, p1, hb1, mask0, beta1, IN_, d1);
    fw2_add<<<(H1_ * H2_ + 255) / 256, 256>>>(alpha2);
    sgemm_fwd<3, true, false><<<gF, 256>>>(s1, fw2, H1_, d1, nullptr, eta2,
                                           nullptr, nullptr, m2, s2, p2);
    sgemm_hebb<<<gH2, 256>>>(s1, p2, hb2, mask1, beta2, H1_, d1);

    // ---- step 2 (hebb updates skipped: never consumed) ----
    sgemm_fwd<2, false, false><<<gF, 256>>>(x, hb1, IN_, d2, alpha1, eta1,
                                            C1, nullptr, m1, s1, p1);
    fw2_add<<<(H1_ * H2_ + 255) / 256, 256>>>(alpha2);
    sgemm_fwd<3, false, false><<<gF, 256>>>(s1, fw2, H1_, d2, nullptr, eta2,
                                            nullptr, nullptr, m2, s2, p2);

    // ---- output ----
    out_gemm<<<B_ / 8, 256>>>(m2, Wm3, out);
}

// round 7
// speedup vs baseline: 1.2810x; 1.2810x over previous
#include <cuda_runtime.h>
#include <cuda_bf16.h>
#include <math.h>
#include <stdint.h>

using bf16 = __nv_bfloat16;

static constexpr int B_   = 8192;
static constexpr int IN_  = 784;
static constexpr int INP_ = 832;     // IN padded to multiple of 64 (for HMMA hebb)
static constexpr int H1_  = 1024;
static constexpr int H2_  = 1024;
static constexpr int OUT_ = 10;

// ------------------------------ asm helpers (hebb HMMA) --------------------
__device__ __forceinline__ uint32_t cvta_smem(const void* p) {
    uint32_t a;
    asm("{ .reg .u64 t; cvta.to.shared.u64 t, %1; cvt.u32.u64 %0, t; }"
        : "=r"(a) : "l"(p));
    return a;
}
__device__ __forceinline__ void cp16(uint32_t dst, const void* src) {
    asm volatile("cp.async.cg.shared.global [%0], [%1], 16;"
                 :: "r"(dst), "l"(src));
}
__device__ __forceinline__ void cp_commit() {
    asm volatile("cp.async.commit_group;" ::: "memory");
}
template <int N>
__device__ __forceinline__ void cp_wait() {
    asm volatile("cp.async.wait_group %0;" :: "n"(N) : "memory");
}
__device__ __forceinline__ void ldm_x4_t(uint32_t* r, uint32_t a) {
    asm volatile("ldmatrix.sync.aligned.m8n8.x4.trans.shared.b16 {%0,%1,%2,%3}, [%4];"
                 : "=r"(r[0]), "=r"(r[1]), "=r"(r[2]), "=r"(r[3]) : "r"(a));
}
__device__ __forceinline__ void mma16816(float* c, const uint32_t a[4],
                                         const uint32_t b[2]) {
    asm volatile(
        "mma.sync.aligned.m16n8k16.row.col.f32.bf16.bf16.f32 "
        "{%0,%1,%2,%3}, {%4,%5,%6,%7}, {%8,%9}, {%0,%1,%2,%3};"
        : "+f"(c[0]), "+f"(c[1]), "+f"(c[2]), "+f"(c[3])
        : "r"(a[0]), "r"(a[1]), "r"(a[2]), "r"(a[3]), "r"(b[0]), "r"(b[1]));
}

// ------------------------------ device scratch -----------------------------
__device__ __align__(16) bf16 g_xh [(size_t)B_ * INP_];
__device__ __align__(16) bf16 g_xm [(size_t)B_ * INP_];
__device__ __align__(16) bf16 g_s1bf[(size_t)B_ * H1_];
__device__ __align__(16) bf16 g_p1h[(size_t)B_ * H1_];
__device__ __align__(16) bf16 g_p1l[(size_t)B_ * H1_];
__device__ __align__(16) bf16 g_p2h[(size_t)B_ * H2_];
__device__ __align__(16) bf16 g_p2l[(size_t)B_ * H2_];
__device__ float g_Wm1[IN_ * H1_];
__device__ float g_Wm2[H1_ * H2_];
__device__ float g_Wm3[H2_ * OUT_];
__device__ float g_fw2[H1_ * H2_];
__device__ float g_C1 [(size_t)B_ * H1_];
__device__ float g_m1 [(size_t)B_ * H1_];
__device__ float g_s1 [(size_t)B_ * H1_];
__device__ float g_m2 [(size_t)B_ * H2_];
__device__ float g_s2 [(size_t)B_ * H2_];
__device__ float g_hb1[IN_ * H1_];
__device__ float g_hb2[H1_ * H2_];

// ------------------------------ prep kernels (round-1 proven) --------------
__global__ void prep_wt(const float* __restrict__ W, const float* __restrict__ mask,
                        float* __restrict__ out, int Kdim, int Ndim) {
    int idx = blockIdx.x * blockDim.x + threadIdx.x;
    int total = Kdim * Ndim;
    if (idx < total) {
        int k = idx / Ndim;
        int n = idx - k * Ndim;
        out[idx] = W[(size_t)n * Kdim + k] * mask[idx];
    }
}

__global__ void zero_hebb() {
    int idx = blockIdx.x * blockDim.x + threadIdx.x;
    if (idx < IN_ * H1_) g_hb1[idx] = 0.0f;
    if (idx < H1_ * H2_) g_hb2[idx] = 0.0f;
}

__global__ void fw2_add(const float* __restrict__ alpha2) {
    int idx = blockIdx.x * blockDim.x + threadIdx.x;
    if (idx < H1_ * H2_) g_fw2[idx] = fmaf(alpha2[0], g_hb2[idx], g_Wm2[idx]);
}

// x 2-split (pitch INP_, zero-padded) for the hebb HMMA A-operand
__global__ void split_x(const float* __restrict__ x) {
    size_t idx = (size_t)blockIdx.x * blockDim.x + threadIdx.x;
    if (idx >= (size_t)B_ * INP_) return;
    int m = (int)(idx / INP_), k = (int)(idx % INP_);
    float v = (k < IN_) ? x[(size_t)m * IN_ + k] : 0.0f;
    bf16 h = __float2bfloat16(v);
    g_xh[idx] = h;
    g_xm[idx] = __float2bfloat16(v - __bfloat162float(h));
}

// ---------------------------------------------------------------------------
// Forward SGEMM (round-1 verbatim math): fused SNN epilogue. mem arithmetic
// is bitwise identical to round 1; epilogue additionally emits bf16 post
// hi/lo pairs and bf16 spikes for the HMMA hebb kernels.
// EP 1: st = acc, store C1; EP 2: st = d*(C1 + alpha*acc); EP 3: st = d*acc
// ---------------------------------------------------------------------------
template <int EP, bool POST, bool FIRST, bool SPKBF>
__global__ void __launch_bounds__(256)
sgemm_fwd(const float* __restrict__ A, const float* __restrict__ Bw, int K,
          float dscale,
          const float* __restrict__ alpha,
          const float* __restrict__ eta,
          const float* __restrict__ C1in,
          float* __restrict__ C1out,
          float* __restrict__ memA, float* __restrict__ spkA,
          bf16* __restrict__ postH, bf16* __restrict__ postL,
          bf16* __restrict__ spkBf) {
    constexpr int BM = 128, BN = 128, BK = 8, N = 1024;
    __shared__ float As[BK][BM];
    __shared__ float Bs[BK][BN];

    const int tid = threadIdx.x;
    const int bm = blockIdx.y, bn = blockIdx.x;

    const float* Ablk = A + (size_t)bm * BM * K;
    const float* Bblk = Bw + bn * BN;

    const int arow = tid >> 1;
    const int acol = (tid & 1) * 4;
    const int brow = tid >> 5;
    const int bcol = (tid & 31) * 4;

    const int tm0 = (tid >> 4) * 8;
    const int tn0 = (tid & 15) * 8;

    float acc[8][8];
#pragma unroll
    for (int i = 0; i < 8; i++)
#pragma unroll
        for (int j = 0; j < 8; j++) acc[i][j] = 0.0f;

    for (int k0 = 0; k0 < K; k0 += BK) {
        float4 av = *reinterpret_cast<const float4*>(Ablk + (size_t)arow * K + k0 + acol);
        float4 bv = *reinterpret_cast<const float4*>(Bblk + (size_t)(k0 + brow) * N + bcol);
        As[acol + 0][arow] = av.x;
        As[acol + 1][arow] = av.y;
        As[acol + 2][arow] = av.z;
        As[acol + 3][arow] = av.w;
        *reinterpret_cast<float4*>(&Bs[brow][bcol]) = bv;
        __syncthreads();
#pragma unroll
        for (int kk = 0; kk < BK; ++kk) {
            float4 a0 = *reinterpret_cast<const float4*>(&As[kk][tm0]);
            float4 a1 = *reinterpret_cast<const float4*>(&As[kk][tm0 + 4]);
            float4 b0 = *reinterpret_cast<const float4*>(&Bs[kk][tn0]);
            float4 b1 = *reinterpret_cast<const float4*>(&Bs[kk][tn0 + 4]);
            float ra[8] = {a0.x, a0.y, a0.z, a0.w, a1.x, a1.y, a1.z, a1.w};
            float rb[8] = {b0.x, b0.y, b0.z, b0.w, b1.x, b1.y, b1.z, b1.w};
#pragma unroll
            for (int i = 0; i < 8; i++)
#pragma unroll
                for (int j = 0; j < 8; j++)
                    acc[i][j] = fmaf(ra[i], rb[j], acc[i][j]);
        }
        __syncthreads();
    }

    // ---- fused epilogue (round-1 mem math, bitwise) ----
    const float alphaV = (EP == 2) ? alpha[0] : 0.0f;
    const int ncol0 = bn * BN + tn0;
    float et[8];
#pragma unroll
    for (int jj = 0; jj < 8; jj += 4) {
        float4 ev = *reinterpret_cast<const float4*>(&eta[ncol0 + jj]);
        et[jj + 0] = ev.x; et[jj + 1] = ev.y; et[jj + 2] = ev.z; et[jj + 3] = ev.w;
    }

#pragma unroll
    for (int i = 0; i < 8; i++) {
        size_t base = (size_t)(bm * BM + tm0 + i) * N + ncol0;
#pragma unroll
        for (int jj = 0; jj < 8; jj += 4) {
            float st[4], mmv[4], spv[4], pov[4];
            float c1v[4], omv[4], osv[4];
            if (EP == 2) {
                float4 cv = *reinterpret_cast<const float4*>(C1in + base + jj);
                c1v[0] = cv.x; c1v[1] = cv.y; c1v[2] = cv.z; c1v[3] = cv.w;
            }
            if (!FIRST) {
                float4 mv = *reinterpret_cast<const float4*>(memA + base + jj);
                float4 sv = *reinterpret_cast<const float4*>(spkA + base + jj);
                omv[0] = mv.x; omv[1] = mv.y; omv[2] = mv.z; omv[3] = mv.w;
                osv[0] = sv.x; osv[1] = sv.y; osv[2] = sv.z; osv[3] = sv.w;
            }
#pragma unroll
            for (int j = 0; j < 4; j++) {
                float a = acc[i][jj + j];
                if (EP == 1)      st[j] = a;
                else if (EP == 2) st[j] = dscale * (c1v[j] + alphaV * a);
                else              st[j] = dscale * a;
                float mem = FIRST ? st[j]
                                  : (omv[j] - osv[j] * 0.5f) * 0.8f + st[j];
                mmv[j] = mem;
                spv[j] = ((mem - 0.5f) > 0.0f) ? 1.0f : 0.0f;
                if (POST) pov[j] = tanhf(2.0f * mem - et[jj + j]);
            }
            if (EP == 1)
                *reinterpret_cast<float4*>(C1out + base + jj) =
                    make_float4(acc[i][jj], acc[i][jj + 1], acc[i][jj + 2], acc[i][jj + 3]);
            *reinterpret_cast<float4*>(memA + base + jj) =
                make_float4(mmv[0], mmv[1], mmv[2], mmv[3]);
            *reinterpret_cast<float4*>(spkA + base + jj) =
                make_float4(spv[0], spv[1], spv[2], spv[3]);
            if (POST) {
                ushort4 uh, ul;
                bf16 h0 = __float2bfloat16(pov[0]);
                bf16 h1 = __float2bfloat16(pov[1]);
                bf16 h2 = __float2bfloat16(pov[2]);
                bf16 h3 = __float2bfloat16(pov[3]);
                uh.x = __bfloat16_as_ushort(h0);
                uh.y = __bfloat16_as_ushort(h1);
                uh.z = __bfloat16_as_ushort(h2);
                uh.w = __bfloat16_as_ushort(h3);
                ul.x = __bfloat16_as_ushort(__float2bfloat16(pov[0] - __bfloat162float(h0)));
                ul.y = __bfloat16_as_ushort(__float2bfloat16(pov[1] - __bfloat162float(h1)));
                ul.z = __bfloat16_as_ushort(__float2bfloat16(pov[2] - __bfloat162float(h2)));
                ul.w = __bfloat16_as_ushort(__float2bfloat16(pov[3] - __bfloat162float(h3)));
                *reinterpret_cast<ushort4*>(postH + base + jj) = uh;
                *reinterpret_cast<ushort4*>(postL + base + jj) = ul;
            }
            if (SPKBF) {
                ushort4 us;
                us.x = __bfloat16_as_ushort(__float2bfloat16(spv[0]));
                us.y = __bfloat16_as_ushort(__float2bfloat16(spv[1]));
                us.z = __bfloat16_as_ushort(__float2bfloat16(spv[2]));
                us.w = __bfloat16_as_ushort(__float2bfloat16(spv[3]));
                *reinterpret_cast<ushort4*>(spkBf + base + jj) = us;
            }
        }
    }
}

// ---------------------------------------------------------------------------
// Hebb HMMA GEMM (round-5 kernel, exonerated by round-6 A/B result):
// Hb(M x 1024) = 0.8*Hb + (1-mask)*beta[m]*(d/8192)*sum_p A[pa]^T @ P[pp]
// A splits: (8192 x Mpitch) bf16 k-major.  P splits: (8192 x 1024) bf16 k-major.
// NP=3: (A0*P0, A0*P1, A1*P0)   NP=2: (A0*P0, A0*P1)
// ---------------------------------------------------------------------------
template <int NP>
__global__ void __launch_bounds__(256)
tc_hebb(const bf16* __restrict__ A0, const bf16* __restrict__ A1,
        int Mpitch, int M,
        const bf16* __restrict__ P0, const bf16* __restrict__ P1,
        float* __restrict__ Hb, const float* __restrict__ mask,
        const float* __restrict__ beta, float dscale) {
    __shared__ __align__(16) bf16 sA[2][32 * 72];
    __shared__ __align__(16) bf16 sP[2][32 * 72];
    const int tid = threadIdx.x, lane = tid & 31, wid = tid >> 5;
    const int wm = wid & 3, wn = wid >> 2;           // 4 x 2 warp grid (m16 x n32)
    const int m0b = blockIdx.y * 64, n0b = blockIdx.x * 64;
    const uint32_t aB0 = cvta_smem(&sA[0][0]);
    const uint32_t pB0 = cvta_smem(&sP[0][0]);
    constexpr uint32_t STG = 32 * 72 * 2;

    const bf16* Ap[2] = {A0, A1};
    const bf16* Pp[2] = {P0, P1};
    const int pa[3] = {0, 0, 1};
    const int pp[3] = {0, 1, 0};

    const int srow = tid >> 3, sc = tid & 7;

    float acc[4][4];
#pragma unroll
    for (int j = 0; j < 4; ++j)
#pragma unroll
        for (int q = 0; q < 4; ++q) acc[j][q] = 0.0f;

    constexpr int KC = 8192 / 32;
    constexpr int V = NP * KC;

    auto issue = [&](int v, int s) {
        int p = v >> 8, c = v & (KC - 1);
        const bf16* ag = Ap[pa[p]] + (size_t)(c * 32 + srow) * Mpitch + m0b + sc * 8;
        const bf16* pg = Pp[pp[p]] + (size_t)(c * 32 + srow) * 1024 + n0b + sc * 8;
        uint32_t off = (uint32_t)(srow * 72 + sc * 8) * 2 + (uint32_t)s * STG;
        cp16(aB0 + off, ag);
        cp16(pB0 + off, pg);
        cp_commit();
    };

    issue(0, 0);
    issue(1, 1);
    int s = 0;
    for (int v = 0; v < V; ++v) {
        if (v + 1 < V) cp_wait<1>(); else cp_wait<0>();
        __syncthreads();
        const uint32_t aB = aB0 + (uint32_t)s * STG;
        const uint32_t pB = pB0 + (uint32_t)s * STG;
#pragma unroll
        for (int kk = 0; kk < 2; ++kk) {
            uint32_t af[4];
            {
                int krow = kk * 16 + ((lane >> 4) & 1) * 8 + (lane & 7);
                int mcol = wm * 16 + ((lane >> 3) & 1) * 8;
                ldm_x4_t(af, aB + (uint32_t)(krow * 72 + mcol) * 2);
            }
            uint32_t bf_[4][2];
#pragma unroll
            for (int jj = 0; jj < 2; ++jj) {
                uint32_t r[4];
                int krow = kk * 16 + ((lane >> 3) & 1) * 8 + (lane & 7);
                int ncol = wn * 32 + jj * 16 + ((lane >> 4) & 1) * 8;
                ldm_x4_t(r, pB + (uint32_t)(krow * 72 + ncol) * 2);
                bf_[jj * 2][0] = r[0]; bf_[jj * 2][1] = r[1];
                bf_[jj * 2 + 1][0] = r[2]; bf_[jj * 2 + 1][1] = r[3];
            }
#pragma unroll
            for (int j = 0; j < 4; ++j)
                mma16816(acc[j], af, bf_[j]);
        }
        __syncthreads();
        if (v + 2 < V) issue(v + 2, s);
        s ^= 1;
    }

    const float inv = dscale * (1.0f / 8192.0f);
#pragma unroll
    for (int h = 0; h < 2; ++h) {
        const int m = m0b + wm * 16 + (lane >> 2) + h * 8;
        if (m < M) {
            const float bs = beta[m] * inv;
            const size_t roff = (size_t)m * 1024;
#pragma unroll
            for (int j = 0; j < 4; ++j) {
                const int n = n0b + wn * 32 + j * 8 + (lane & 3) * 2;
                const size_t idx = roff + n;
                float2 hb = *reinterpret_cast<const float2*>(Hb + idx);
                float2 mk = *reinterpret_cast<const float2*>(mask + idx);
                hb.x = 0.8f * hb.x + (1.0f - mk.x) * bs * acc[j][h * 2 + 0];
                hb.y = 0.8f * hb.y + (1.0f - mk.y) * bs * acc[j][h * 2 + 1];
                *reinterpret_cast<float2*>(Hb + idx) = hb;
            }
        }
    }
}

// ---------------------------------------------------------------------------
// Output GEMM: out(8192 x 10) = m2 @ Wm3   (fp32 SIMT, round-1 verbatim)
// ---------------------------------------------------------------------------
__global__ void __launch_bounds__(256)
out_gemm(const float* __restrict__ m2, const float* __restrict__ Wm3,
         float* __restrict__ out) {
    __shared__ float sW[H2_ * OUT_];
    const int tid = threadIdx.x;
    for (int i = tid; i < H2_ * OUT_; i += blockDim.x) sW[i] = Wm3[i];
    __syncthreads();

    const int warp = tid >> 5, lane = tid & 31;
    const int b = blockIdx.x * 8 + warp;
    const float* row = m2 + (size_t)b * H2_;

    float acc[OUT_];
#pragma unroll
    for (int j = 0; j < OUT_; j++) acc[j] = 0.0f;
    for (int k = lane; k < H2_; k += 32) {
        float v = row[k];
#pragma unroll
        for (int j = 0; j < OUT_; j++) acc[j] = fmaf(v, sW[k * OUT_ + j], acc[j]);
    }
#pragma unroll
    for (int j = 0; j < OUT_; j++) {
        float sv = acc[j];
#pragma unroll
        for (int o = 16; o > 0; o >>= 1) sv += __shfl_xor_sync(0xffffffffu, sv, o);
        if (lane == 0) out[(size_t)b * OUT_ + j] = sv;
    }
}

// ---------------------------------------------------------------------------
extern "C" void kernel_launch(void* const* d_in, const int* in_sizes, int n_in,
                              void* d_out, int out_size) {
    const float* x      = (const float*)d_in[0];
    const float* mask0  = (const float*)d_in[1];
    const float* mask1  = (const float*)d_in[2];
    const float* mask2  = (const float*)d_in[3];
    const float* fc1    = (const float*)d_in[4];
    const float* fc2    = (const float*)d_in[5];
    const float* fc3    = (const float*)d_in[6];
    const float* alpha1 = (const float*)d_in[7];
    const float* alpha2 = (const float*)d_in[8];
    const float* beta1  = (const float*)d_in[9];
    const float* beta2  = (const float*)d_in[10];
    const float* eta1   = (const float*)d_in[11];
    const float* eta2   = (const float*)d_in[12];
    float* out = (float*)d_out;

    bf16 *xh, *xm, *s1bf, *p1h, *p1l, *p2h, *p2l;
    float *Wm1, *Wm2, *Wm3, *fw2, *C1, *m1, *s1, *m2, *s2, *hb1, *hb2;
    cudaGetSymbolAddress((void**)&xh,   g_xh);
    cudaGetSymbolAddress((void**)&xm,   g_xm);
    cudaGetSymbolAddress((void**)&s1bf, g_s1bf);
    cudaGetSymbolAddress((void**)&p1h,  g_p1h);
    cudaGetSymbolAddress((void**)&p1l,  g_p1l);
    cudaGetSymbolAddress((void**)&p2h,  g_p2h);
    cudaGetSymbolAddress((void**)&p2l,  g_p2l);
    cudaGetSymbolAddress((void**)&Wm1,  g_Wm1);
    cudaGetSymbolAddress((void**)&Wm2,  g_Wm2);
    cudaGetSymbolAddress((void**)&Wm3,  g_Wm3);
    cudaGetSymbolAddress((void**)&fw2,  g_fw2);
    cudaGetSymbolAddress((void**)&C1,   g_C1);
    cudaGetSymbolAddress((void**)&m1,   g_m1);
    cudaGetSymbolAddress((void**)&s1,   g_s1);
    cudaGetSymbolAddress((void**)&m2,   g_m2);
    cudaGetSymbolAddress((void**)&s2,   g_s2);
    cudaGetSymbolAddress((void**)&hb1,  g_hb1);
    cudaGetSymbolAddress((void**)&hb2,  g_hb2);

    const float d0 = 1.0f;
    const float d1 = 0.98019867330675525f;   // float32(exp(-1/50))
    const float d2 = 0.96078943915232320f;   // float32(exp(-2/50))

    // ---- prep ----
    zero_hebb<<<(H1_ * H2_ + 255) / 256, 256>>>();
    split_x<<<(int)(((size_t)B_ * INP_ + 255) / 256), 256>>>(x);
    prep_wt<<<(IN_ * H1_ + 255) / 256, 256>>>(fc1, mask0, Wm1, IN_, H1_);
    prep_wt<<<(H1_ * H2_ + 255) / 256, 256>>>(fc2, mask1, Wm2, H1_, H2_);
    prep_wt<<<(H2_ * OUT_ + 255) / 256, 256>>>(fc3, mask2, Wm3, H2_, OUT_);

    dim3 gF(H1_ / 128, B_ / 128);            // (8, 64)
    dim3 gH1(16, 13);                        // hebb1 64x64 tiles over (784,1024)
    dim3 gH2(16, 16);                        // hebb2 over (1024,1024)

    // ---- step 0 (d=1, hebb=0) ----
    sgemm_fwd<1, true, true, true><<<gF, 256>>>(
        x, Wm1, IN_, d0, nullptr, eta1, nullptr, C1, m1, s1, p1h, p1l, s1bf);
    tc_hebb<3><<<gH1, 256>>>(xh, xm, INP_, IN_, p1h, p1l, hb1, mask0, beta1, d0);
    sgemm_fwd<3, true, true, false><<<gF, 256>>>(
        s1, Wm2, H1_, d0, nullptr, eta2, nullptr, nullptr, m2, s2, p2h, p2l, nullptr);
    tc_hebb<2><<<gH2, 256>>>(s1bf, nullptr, H1_, H1_, p2h, p2l, hb2, mask1, beta2, d0);

    // ---- step 1 ----
    sgemm_fwd<2, true, false, true><<<gF, 256>>>(
        x, hb1, IN_, d1, alpha1, eta1, C1, nullptr, m1, s1, p1h, p1l, s1bf);
    tc_hebb<3><<<gH1, 256>>>(xh, xm, INP_, IN_, p1h, p1l, hb1, mask0, beta1, d1);
    fw2_add<<<(H1_ * H2_ + 255) / 256, 256>>>(alpha2);
    sgemm_fwd<3, true, false, false><<<gF, 256>>>(
        s1, fw2, H1_, d1, nullptr, eta2, nullptr, nullptr, m2, s2, p2h, p2l, nullptr);
    tc_hebb<2><<<gH2, 256>>>(s1bf, nullptr, H1_, H1_, p2h, p2l, hb2, mask1, beta2, d1);

    // ---- step 2 (final hebb updates skipped: never consumed) ----
    sgemm_fwd<2, false, false, false><<<gF, 256>>>(
        x, hb1, IN_, d2, alpha1, eta1, C1, nullptr, m1, s1, nullptr, nullptr, nullptr);
    fw2_add<<<(H1_ * H2_ + 255) / 256, 256>>>(alpha2);
    sgemm_fwd<3, false, false, false><<<gF, 256>>>(
        s1, fw2, H1_, d2, nullptr, eta2, nullptr, nullptr, m2, s2, nullptr, nullptr, nullptr);

    // ---- output ----
    out_gemm<<<B_ / 8, 256>>>(m2, Wm3, out);
}

// round 9
// speedup vs baseline: 1.5252x; 1.1907x over previous
#include <cuda_runtime.h>
#include <cuda_bf16.h>
#include <math.h>
#include <stdint.h>

using bf16 = __nv_bfloat16;

static constexpr int B_   = 8192;
static constexpr int IN_  = 784;
static constexpr int INP_ = 832;     // IN padded to multiple of 64
static constexpr int H1_  = 1024;
static constexpr int H2_  = 1024;
static constexpr int OUT_ = 10;

// ------------------------------ asm helpers -------------------------------
__device__ __forceinline__ uint32_t cvta_smem(const void* p) {
    uint32_t a;
    asm("{ .reg .u64 t; cvta.to.shared.u64 t, %1; cvt.u32.u64 %0, t; }"
        : "=r"(a) : "l"(p));
    return a;
}
__device__ __forceinline__ void cp16(uint32_t dst, const void* src) {
    asm volatile("cp.async.cg.shared.global [%0], [%1], 16;"
                 :: "r"(dst), "l"(src));
}
__device__ __forceinline__ void cp_commit() {
    asm volatile("cp.async.commit_group;" ::: "memory");
}
template <int N>
__device__ __forceinline__ void cp_wait() {
    asm volatile("cp.async.wait_group %0;" :: "n"(N) : "memory");
}
__device__ __forceinline__ void ldm_x4_t(uint32_t* r, uint32_t a) {
    asm volatile("ldmatrix.sync.aligned.m8n8.x4.trans.shared.b16 {%0,%1,%2,%3}, [%4];"
                 : "=r"(r[0]), "=r"(r[1]), "=r"(r[2]), "=r"(r[3]) : "r"(a));
}
__device__ __forceinline__ void mma16816(float* c, const uint32_t a[4],
                                         const uint32_t b[2]) {
    asm volatile(
        "mma.sync.aligned.m16n8k16.row.col.f32.bf16.bf16.f32 "
        "{%0,%1,%2,%3}, {%4,%5,%6,%7}, {%8,%9}, {%0,%1,%2,%3};"
        : "+f"(c[0]), "+f"(c[1]), "+f"(c[2]), "+f"(c[3])
        : "r"(a[0]), "r"(a[1]), "r"(a[2]), "r"(a[3]), "r"(b[0]), "r"(b[1]));
}

// product tables (PSET 0: 3x3 triangle; 1: 2x2 triangle; 2: exact-A x 3 B)
__device__ __constant__ int c_pa[3][6] = {
    {0, 0, 1, 1, 0, 2},
    {0, 0, 1, 0, 0, 0},
    {0, 0, 0, 0, 0, 0}
};
__device__ __constant__ int c_pb[3][6] = {
    {0, 1, 0, 1, 2, 0},
    {0, 1, 0, 0, 0, 0},
    {0, 1, 2, 0, 0, 0}
};

// ------------------------------ device scratch -----------------------------
__device__ __align__(16) bf16 g_xh  [(size_t)B_ * INP_];   // natural (B, INP)
__device__ __align__(16) bf16 g_xm  [(size_t)B_ * INP_];
__device__ __align__(16) bf16 g_xth [(size_t)INP_ * B_];   // transposed (INP, B)
__device__ __align__(16) bf16 g_xtm [(size_t)INP_ * B_];
__device__ __align__(16) bf16 g_xtl [(size_t)INP_ * B_];
__device__ __align__(16) bf16 g_w1kh[INP_ * H1_];          // k-major (INP, H1)
__device__ __align__(16) bf16 g_w1km[INP_ * H1_];
__device__ __align__(16) bf16 g_w1kl[INP_ * H1_];
__device__ __align__(16) bf16 g_f2kh[H1_ * H2_];           // k-major (H1, H2)
__device__ __align__(16) bf16 g_f2km[H1_ * H2_];
__device__ __align__(16) bf16 g_f2kl[H1_ * H2_];
__device__ __align__(16) bf16 g_ab1h[INP_ * H1_];          // k-major (INP, H1)
__device__ __align__(16) bf16 g_ab1l[INP_ * H1_];
__device__ __align__(16) bf16 g_s1t [(size_t)H1_ * B_];    // spikes transposed
__device__ __align__(16) bf16 g_s1bf[(size_t)B_ * H1_];    // spikes natural
__device__ __align__(16) bf16 g_p1h [(size_t)B_ * H1_];
__device__ __align__(16) bf16 g_p1l [(size_t)B_ * H1_];
__device__ __align__(16) bf16 g_p2h [(size_t)B_ * H2_];
__device__ __align__(16) bf16 g_p2l [(size_t)B_ * H2_];
__device__ float g_Wm3[H2_ * OUT_];
__device__ float g_C1 [(size_t)B_ * H1_];
__device__ float g_m1 [(size_t)B_ * H1_];
__device__ float g_s1 [(size_t)B_ * H1_];
__device__ float g_m2 [(size_t)B_ * H2_];
__device__ float g_s2 [(size_t)B_ * H2_];
__device__ float g_hb1[IN_ * H1_];
__device__ float g_hb2[H1_ * H2_];

// ------------------------------ prep kernels -------------------------------
__device__ __forceinline__ void split3(float v, bf16& h, bf16& m, bf16& l) {
    h = __float2bfloat16(v);
    float r = v - __bfloat162float(h);
    m = __float2bfloat16(r);
    l = __float2bfloat16(r - __bfloat162float(m));
}

__global__ void zero_hebb() {
    int idx = blockIdx.x * blockDim.x + threadIdx.x;
    if (idx < IN_ * H1_) g_hb1[idx] = 0.0f;
    if (idx < H1_ * H2_) g_hb2[idx] = 0.0f;
}

// natural 2-split of x (A-operand for hebb1)
__global__ void split_x(const float* __restrict__ x) {
    size_t idx = (size_t)blockIdx.x * blockDim.x + threadIdx.x;
    if (idx >= (size_t)B_ * INP_) return;
    int m = (int)(idx / INP_), k = (int)(idx % INP_);
    float v = (k < IN_) ? x[(size_t)m * IN_ + k] : 0.0f;
    bf16 h = __float2bfloat16(v);
    g_xh[idx] = h;
    g_xm[idx] = __float2bfloat16(v - __bfloat162float(h));
}

// tiled transpose + 3-split of x -> (INP, B)
__global__ void split_xt(const float* __restrict__ x) {
    __shared__ float t[32][33];
    const int kb = blockIdx.x * 32, mb = blockIdx.y * 32;
#pragma unroll
    for (int r = 0; r < 32; r += 8) {
        int m = mb + threadIdx.y + r, k = kb + threadIdx.x;
        t[threadIdx.y + r][threadIdx.x] =
            (k < IN_) ? x[(size_t)m * IN_ + k] : 0.0f;
    }
    __syncthreads();
#pragma unroll
    for (int r = 0; r < 32; r += 8) {
        int k = kb + threadIdx.y + r, m = mb + threadIdx.x;
        float v = t[threadIdx.x][threadIdx.y + r];
        size_t o = (size_t)k * B_ + m;
        split3(v, g_xth[o], g_xtm[o], g_xtl[o]);
    }
}

// W1 masked, k-major 3-split: w1k[k*H1+n] = fc1[n][k]*mask0[k][n]
__global__ void prep_w1k(const float* __restrict__ fc1, const float* __restrict__ mask0) {
    int idx = blockIdx.x * blockDim.x + threadIdx.x;
    if (idx >= INP_ * H1_) return;
    int k = idx / H1_, n = idx % H1_;
    float v = (k < IN_) ? fc1[n * IN_ + k] * mask0[k * H1_ + n] : 0.0f;
    split3(v, g_w1kh[idx], g_w1km[idx], g_w1kl[idx]);
}

// fw2 = W2m + alpha2*hb2, k-major 3-split
__global__ void prep_f2k(const float* __restrict__ fc2, const float* __restrict__ mask1,
                         const float* __restrict__ alpha2) {
    int idx = blockIdx.x * blockDim.x + threadIdx.x;
    if (idx >= H1_ * H2_) return;
    int k = idx / H2_, n = idx % H2_;
    float v = fmaf(alpha2[0], g_hb2[idx], fc2[n * H1_ + k] * mask1[idx]);
    split3(v, g_f2kh[idx], g_f2km[idx], g_f2kl[idx]);
}

// ab1 = alpha1*hb1, k-major 2-split
__global__ void prep_ab1(const float* __restrict__ alpha1) {
    int idx = blockIdx.x * blockDim.x + threadIdx.x;
    if (idx >= INP_ * H1_) return;
    int k = idx / H1_, n = idx % H1_;
    float v = (k < IN_) ? alpha1[0] * g_hb1[k * H1_ + n] : 0.0f;
    bf16 h = __float2bfloat16(v);
    g_ab1h[idx] = h;
    g_ab1l[idx] = __float2bfloat16(v - __bfloat162float(h));
}

__global__ void prep_w3(const float* __restrict__ fc3, const float* __restrict__ mask2) {
    int idx = blockIdx.x * blockDim.x + threadIdx.x;
    if (idx >= H2_ * OUT_) return;
    int k = idx / OUT_, n = idx - k * OUT_;
    g_Wm3[idx] = fc3[n * H2_ + k] * mask2[idx];
}

// ---------------------------------------------------------------------------
// Forward HMMA GEMM, trans-ldmatrix path, with TWO-LEVEL ACCUMULATION:
// the mma.sync accumulator (non-IEEE RZ adds) is promoted into an fp32
// register accumulator via IEEE adds after EVERY 32-k chunk, killing the
// linear RZ bias that produced the 4.5e-3 failures.
// CTA tile 128x64, warps 4x2 (m32 x n32 each).
// C(M=8192, N=1024) = sum_p A[pa]^T @ B[pb]
// A splits: (Kpad, B_) bf16 k-major pitch B_.  B splits: (Kpad, 1024) k-major.
// EP 1: st = acc (C1out = acc); EP 2: st = d*(C1in + acc); EP 3: st = d*acc
// ---------------------------------------------------------------------------
template <int PSET, int EP, bool POST, bool FIRST, bool SPKT>
__global__ void __launch_bounds__(256, 2)
tcf(const bf16* __restrict__ A0, const bf16* __restrict__ A1,
    const bf16* __restrict__ A2,
    const bf16* __restrict__ B0, const bf16* __restrict__ B1,
    const bf16* __restrict__ B2,
    int Kpad, float dscale, const float* __restrict__ eta,
    const float* __restrict__ C1in, float* __restrict__ C1out,
    float* __restrict__ memA, float* __restrict__ spkA,
    bf16* __restrict__ postH, bf16* __restrict__ postL,
    bf16* __restrict__ spkBf, bf16* __restrict__ spkT) {
    constexpr int NP = (PSET == 0) ? 6 : 3;
    __shared__ __align__(16) bf16 sA[2][32 * 136];
    __shared__ __align__(16) bf16 sB[2][32 * 72];

    const int tid = threadIdx.x, lane = tid & 31, wid = tid >> 5;
    const int wm = wid & 3, wn = wid >> 2;        // 4 x 2 warps (m32 x n32)
    const int bn = blockIdx.x, bm = blockIdx.y;
    const int KC = Kpad >> 5;
    const int V = NP * KC;

    const bf16* Ap[3] = {A0, A1, A2};
    const bf16* Bp[3] = {B0, B1, B2};

    const uint32_t aB0 = cvta_smem(&sA[0][0]);
    const uint32_t bB0 = cvta_smem(&sB[0][0]);
    constexpr uint32_t STGA = 32 * 136 * 2;
    constexpr uint32_t STGB = 32 * 72 * 2;

    const int lr = tid >> 3;          // 0..31 (k row within chunk)
    const int lc = tid & 7;           // col group

    float acc[2][4][4];               // mma accumulator (short chains)
    float accM[2][4][4];              // promoted fp32 accumulator (IEEE adds)
#pragma unroll
    for (int i = 0; i < 2; ++i)
#pragma unroll
        for (int j = 0; j < 4; ++j)
#pragma unroll
            for (int q = 0; q < 4; ++q) { acc[i][j][q] = 0.0f; accM[i][j][q] = 0.0f; }

    auto issue = [&](int v, int s) {
        int p = v / KC, c = v - p * KC;
        const bf16* ag = Ap[c_pa[PSET][p]] + (size_t)(c * 32 + lr) * B_ + bm * 128 + lc * 16;
        const bf16* bg = Bp[c_pb[PSET][p]] + (size_t)(c * 32 + lr) * 1024 + bn * 64 + lc * 8;
        uint32_t offA = (uint32_t)(lr * 136 + lc * 16) * 2 + (uint32_t)s * STGA;
        uint32_t offB = (uint32_t)(lr * 72 + lc * 8) * 2 + (uint32_t)s * STGB;
        cp16(aB0 + offA, ag);
        cp16(aB0 + offA + 16, ag + 8);
        cp16(bB0 + offB, bg);
        cp_commit();
    };

    issue(0, 0);
    issue(1, 1);
    int s = 0;
    for (int v = 0; v < V; ++v) {
        if (v + 1 < V) cp_wait<1>(); else cp_wait<0>();
        __syncthreads();
        const uint32_t aB = aB0 + (uint32_t)s * STGA;
        const uint32_t bB = bB0 + (uint32_t)s * STGB;
#pragma unroll
        for (int kk = 0; kk < 2; ++kk) {
            uint32_t af[2][4];
#pragma unroll
            for (int i = 0; i < 2; ++i) {
                int krow = kk * 16 + ((lane >> 4) & 1) * 8 + (lane & 7);
                int mcol = wm * 32 + i * 16 + ((lane >> 3) & 1) * 8;
                ldm_x4_t(af[i], aB + (uint32_t)(krow * 136 + mcol) * 2);
            }
            uint32_t bf_[4][2];
#pragma unroll
            for (int jj = 0; jj < 2; ++jj) {
                uint32_t r[4];
                int krow = kk * 16 + ((lane >> 3) & 1) * 8 + (lane & 7);
                int ncol = wn * 32 + jj * 16 + ((lane >> 4) & 1) * 8;
                ldm_x4_t(r, bB + (uint32_t)(krow * 72 + ncol) * 2);
                bf_[jj * 2][0] = r[0]; bf_[jj * 2][1] = r[1];
                bf_[jj * 2 + 1][0] = r[2]; bf_[jj * 2 + 1][1] = r[3];
            }
#pragma unroll
            for (int i = 0; i < 2; ++i)
#pragma unroll
                for (int j = 0; j < 4; ++j)
                    mma16816(acc[i][j], af[i], bf_[j]);
        }
        // ---- promotion: IEEE fp32 add, reset mma accumulator ----
#pragma unroll
        for (int i = 0; i < 2; ++i)
#pragma unroll
            for (int j = 0; j < 4; ++j)
#pragma unroll
                for (int q = 0; q < 4; ++q) {
                    accM[i][j][q] += acc[i][j][q];
                    acc[i][j][q] = 0.0f;
                }
        __syncthreads();
        if (v + 2 < V) issue(v + 2, s);
        s ^= 1;
    }

    // -------- fused SNN epilogue (proven mapping + proven math) --------
    const int mbase = bm * 128 + wm * 32;
    const int nbase = bn * 64 + wn * 32;
#pragma unroll
    for (int i = 0; i < 2; ++i) {
#pragma unroll
        for (int h = 0; h < 2; ++h) {
            const int m = mbase + i * 16 + (lane >> 2) + h * 8;
            const size_t roff = (size_t)m * 1024;
#pragma unroll
            for (int j = 0; j < 4; ++j) {
                const int n = nbase + j * 8 + (lane & 3) * 2;
                const size_t idx = roff + n;
                float c0 = accM[i][j][h * 2 + 0];
                float c1 = accM[i][j][h * 2 + 1];
                float st0, st1;
                if (EP == 1) { st0 = c0; st1 = c1; }
                else if (EP == 2) {
                    float2 cv = *reinterpret_cast<const float2*>(C1in + idx);
                    st0 = dscale * (cv.x + c0);
                    st1 = dscale * (cv.y + c1);
                } else { st0 = dscale * c0; st1 = dscale * c1; }
                float m0v, m1v;
                if (FIRST) { m0v = st0; m1v = st1; }
                else {
                    float2 mv = *reinterpret_cast<const float2*>(memA + idx);
                    float2 sv = *reinterpret_cast<const float2*>(spkA + idx);
                    m0v = (mv.x - sv.x * 0.5f) * 0.8f + st0;
                    m1v = (mv.y - sv.y * 0.5f) * 0.8f + st1;
                }
                float sp0 = ((m0v - 0.5f) > 0.0f) ? 1.0f : 0.0f;
                float sp1 = ((m1v - 0.5f) > 0.0f) ? 1.0f : 0.0f;
                *reinterpret_cast<float2*>(memA + idx) = make_float2(m0v, m1v);
                *reinterpret_cast<float2*>(spkA + idx) = make_float2(sp0, sp1);
                if (EP == 1)
                    *reinterpret_cast<float2*>(C1out + idx) = make_float2(c0, c1);
                if (POST) {
                    float2 ev = *reinterpret_cast<const float2*>(eta + n);
                    float p0 = tanhf(2.0f * m0v - ev.x);
                    float p1 = tanhf(2.0f * m1v - ev.y);
                    bf16 ph0 = __float2bfloat16(p0);
                    bf16 ph1 = __float2bfloat16(p1);
                    __nv_bfloat162 hv, lv;
                    hv.x = ph0; hv.y = ph1;
                    lv.x = __float2bfloat16(p0 - __bfloat162float(ph0));
                    lv.y = __float2bfloat16(p1 - __bfloat162float(ph1));
                    *reinterpret_cast<__nv_bfloat162*>(postH + idx) = hv;
                    *reinterpret_cast<__nv_bfloat162*>(postL + idx) = lv;
                }
                if (SPKT) {
                    __nv_bfloat162 sv2;
                    sv2.x = __float2bfloat16(sp0);
                    sv2.y = __float2bfloat16(sp1);
                    *reinterpret_cast<__nv_bfloat162*>(spkBf + idx) = sv2;
                    spkT[(size_t)n * B_ + m]       = sv2.x;
                    spkT[(size_t)(n + 1) * B_ + m] = sv2.y;
                }
            }
        }
    }
}

// ---------------------------------------------------------------------------
// Hebb HMMA GEMM (round-7 PROVEN, verbatim — bias invisible due to ~1e-3
// attenuation of hebb into mem; do not touch)
// ---------------------------------------------------------------------------
template <int NP>
__global__ void __launch_bounds__(256)
tc_hebb(const bf16* __restrict__ A0, const bf16* __restrict__ A1,
        int Mpitch, int M,
        const bf16* __restrict__ P0, const bf16* __restrict__ P1,
        float* __restrict__ Hb, const float* __restrict__ mask,
        const float* __restrict__ beta, float dscale) {
    __shared__ __align__(16) bf16 sA[2][32 * 72];
    __shared__ __align__(16) bf16 sP[2][32 * 72];
    const int tid = threadIdx.x, lane = tid & 31, wid = tid >> 5;
    const int wm = wid & 3, wn = wid >> 2;
    const int m0b = blockIdx.y * 64, n0b = blockIdx.x * 64;
    const uint32_t aB0 = cvta_smem(&sA[0][0]);
    const uint32_t pB0 = cvta_smem(&sP[0][0]);
    constexpr uint32_t STG = 32 * 72 * 2;

    const bf16* Ap[2] = {A0, A1};
    const bf16* Pp[2] = {P0, P1};
    const int pa[3] = {0, 0, 1};
    const int pp[3] = {0, 1, 0};

    const int srow = tid >> 3, sc = tid & 7;

    float acc[4][4];
#pragma unroll
    for (int j = 0; j < 4; ++j)
#pragma unroll
        for (int q = 0; q < 4; ++q) acc[j][q] = 0.0f;

    constexpr int KC = 8192 / 32;
    constexpr int V = NP * KC;

    auto issue = [&](int v, int s) {
        int p = v >> 8, c = v & (KC - 1);
        const bf16* ag = Ap[pa[p]] + (size_t)(c * 32 + srow) * Mpitch + m0b + sc * 8;
        const bf16* pg = Pp[pp[p]] + (size_t)(c * 32 + srow) * 1024 + n0b + sc * 8;
        uint32_t off = (uint32_t)(srow * 72 + sc * 8) * 2 + (uint32_t)s * STG;
        cp16(aB0 + off, ag);
        cp16(pB0 + off, pg);
        cp_commit();
    };

    issue(0, 0);
    issue(1, 1);
    int s = 0;
    for (int v = 0; v < V; ++v) {
        if (v + 1 < V) cp_wait<1>(); else cp_wait<0>();
        __syncthreads();
        const uint32_t aB = aB0 + (uint32_t)s * STG;
        const uint32_t pB = pB0 + (uint32_t)s * STG;
#pragma unroll
        for (int kk = 0; kk < 2; ++kk) {
            uint32_t af[4];
            {
                int krow = kk * 16 + ((lane >> 4) & 1) * 8 + (lane & 7);
                int mcol = wm * 16 + ((lane >> 3) & 1) * 8;
                ldm_x4_t(af, aB + (uint32_t)(krow * 72 + mcol) * 2);
            }
            uint32_t bf_[4][2];
#pragma unroll
            for (int jj = 0; jj < 2; ++jj) {
                uint32_t r[4];
                int krow = kk * 16 + ((lane >> 3) & 1) * 8 + (lane & 7);
                int ncol = wn * 32 + jj * 16 + ((lane >> 4) & 1) * 8;
                ldm_x4_t(r, pB + (uint32_t)(krow * 72 + ncol) * 2);
                bf_[jj * 2][0] = r[0]; bf_[jj * 2][1] = r[1];
                bf_[jj * 2 + 1][0] = r[2]; bf_[jj * 2 + 1][1] = r[3];
            }
#pragma unroll
            for (int j = 0; j < 4; ++j)
                mma16816(acc[j], af, bf_[j]);
        }
        __syncthreads();
        if (v + 2 < V) issue(v + 2, s);
        s ^= 1;
    }

    const float inv = dscale * (1.0f / 8192.0f);
#pragma unroll
    for (int h = 0; h < 2; ++h) {
        const int m = m0b + wm * 16 + (lane >> 2) + h * 8;
        if (m < M) {
            const float bs = beta[m] * inv;
            const size_t roff = (size_t)m * 1024;
#pragma unroll
            for (int j = 0; j < 4; ++j) {
                const int n = n0b + wn * 32 + j * 8 + (lane & 3) * 2;
                const size_t idx = roff + n;
                float2 hb = *reinterpret_cast<const float2*>(Hb + idx);
                float2 mk = *reinterpret_cast<const float2*>(mask + idx);
                hb.x = 0.8f * hb.x + (1.0f - mk.x) * bs * acc[j][h * 2 + 0];
                hb.y = 0.8f * hb.y + (1.0f - mk.y) * bs * acc[j][h * 2 + 1];
                *reinterpret_cast<float2*>(Hb + idx) = hb;
            }
        }
    }
}

// ---------------------------------------------------------------------------
// Output GEMM: out(8192 x 10) = m2 @ Wm3   (fp32 SIMT, proven)
// ---------------------------------------------------------------------------
__global__ void __launch_bounds__(256)
out_gemm(const float* __restrict__ m2, const float* __restrict__ Wm3,
         float* __restrict__ out) {
    __shared__ float sW[H2_ * OUT_];
    const int tid = threadIdx.x;
    for (int i = tid; i < H2_ * OUT_; i += blockDim.x) sW[i] = Wm3[i];
    __syncthreads();

    const int warp = tid >> 5, lane = tid & 31;
    const int b = blockIdx.x * 8 + warp;
    const float* row = m2 + (size_t)b * H2_;

    float acc[OUT_];
#pragma unroll
    for (int j = 0; j < OUT_; j++) acc[j] = 0.0f;
    for (int k = lane; k < H2_; k += 32) {
        float v = row[k];
#pragma unroll
        for (int j = 0; j < OUT_; j++) acc[j] = fmaf(v, sW[k * OUT_ + j], acc[j]);
    }
#pragma unroll
    for (int j = 0; j < OUT_; j++) {
        float sv = acc[j];
#pragma unroll
        for (int o = 16; o > 0; o >>= 1) sv += __shfl_xor_sync(0xffffffffu, sv, o);
        if (lane == 0) out[(size_t)b * OUT_ + j] = sv;
    }
}

// ---------------------------------------------------------------------------
extern "C" void kernel_launch(void* const* d_in, const int* in_sizes, int n_in,
                              void* d_out, int out_size) {
    const float* x      = (const float*)d_in[0];
    const float* mask0  = (const float*)d_in[1];
    const float* mask1  = (const float*)d_in[2];
    const float* mask2  = (const float*)d_in[3];
    const float* fc1    = (const float*)d_in[4];
    const float* fc2    = (const float*)d_in[5];
    const float* fc3    = (const float*)d_in[6];
    const float* alpha1 = (const float*)d_in[7];
    const float* alpha2 = (const float*)d_in[8];
    const float* beta1  = (const float*)d_in[9];
    const float* beta2  = (const float*)d_in[10];
    const float* eta1   = (const float*)d_in[11];
    const float* eta2   = (const float*)d_in[12];
    float* out = (float*)d_out;

    bf16 *xh, *xm, *xth, *xtm, *xtl, *w1kh, *w1km, *w1kl;
    bf16 *f2kh, *f2km, *f2kl, *ab1h, *ab1l, *s1t, *s1bf, *p1h, *p1l, *p2h, *p2l;
    float *Wm3, *C1, *m1, *s1, *m2, *s2, *hb1, *hb2;
    cudaGetSymbolAddress((void**)&xh,   g_xh);
    cudaGetSymbolAddress((void**)&xm,   g_xm);
    cudaGetSymbolAddress((void**)&xth,  g_xth);
    cudaGetSymbolAddress((void**)&xtm,  g_xtm);
    cudaGetSymbolAddress((void**)&xtl,  g_xtl);
    cudaGetSymbolAddress((void**)&w1kh, g_w1kh);
    cudaGetSymbolAddress((void**)&w1km, g_w1km);
    cudaGetSymbolAddress((void**)&w1kl, g_w1kl);
    cudaGetSymbolAddress((void**)&f2kh, g_f2kh);
    cudaGetSymbolAddress((void**)&f2km, g_f2km);
    cudaGetSymbolAddress((void**)&f2kl, g_f2kl);
    cudaGetSymbolAddress((void**)&ab1h, g_ab1h);
    cudaGetSymbolAddress((void**)&ab1l, g_ab1l);
    cudaGetSymbolAddress((void**)&s1t,  g_s1t);
    cudaGetSymbolAddress((void**)&s1bf, g_s1bf);
    cudaGetSymbolAddress((void**)&p1h,  g_p1h);
    cudaGetSymbolAddress((void**)&p1l,  g_p1l);
    cudaGetSymbolAddress((void**)&p2h,  g_p2h);
    cudaGetSymbolAddress((void**)&p2l,  g_p2l);
    cudaGetSymbolAddress((void**)&Wm3,  g_Wm3);
    cudaGetSymbolAddress((void**)&C1,   g_C1);
    cudaGetSymbolAddress((void**)&m1,   g_m1);
    cudaGetSymbolAddress((void**)&s1,   g_s1);
    cudaGetSymbolAddress((void**)&m2,   g_m2);
    cudaGetSymbolAddress((void**)&s2,   g_s2);
    cudaGetSymbolAddress((void**)&hb1,  g_hb1);
    cudaGetSymbolAddress((void**)&hb2,  g_hb2);

    const float d0 = 1.0f;
    const float d1 = 0.98019867330675525f;   // float32(exp(-1/50))
    const float d2 = 0.96078943915232320f;   // float32(exp(-2/50))

    // ---- prep ----
    zero_hebb<<<(H1_ * H2_ + 255) / 256, 256>>>();
    split_x<<<(int)(((size_t)B_ * INP_ + 255) / 256), 256>>>(x);
    split_xt<<<dim3(INP_ / 32, B_ / 32), dim3(32, 8)>>>(x);
    prep_w1k<<<(INP_ * H1_ + 255) / 256, 256>>>(fc1, mask0);
    prep_w3<<<(H2_ * OUT_ + 255) / 256, 256>>>(fc3, mask2);
    prep_f2k<<<(H1_ * H2_ + 255) / 256, 256>>>(fc2, mask1, alpha2);  // hb2 == 0

    dim3 gF(16, 64);       // forward 128x64 tiles over (8192, 1024)
    dim3 gH1(16, 13);      // hebb1 64x64 tiles over (784, 1024)
    dim3 gH2(16, 16);      // hebb2 over (1024, 1024)

    // ---- step 0 ----
    tcf<0, 1, true, true, true><<<gF, 256>>>(
        xth, xtm, xtl, w1kh, w1km, w1kl, INP_, d0, eta1,
        nullptr, C1, m1, s1, p1h, p1l, s1bf, s1t);
    tc_hebb<3><<<gH1, 256>>>(xh, xm, INP_, IN_, p1h, p1l, hb1, mask0, beta1, d0);
    tcf<2, 3, true, true, false><<<gF, 256>>>(
        s1t, nullptr, nullptr, f2kh, f2km, f2kl, H1_, d0, eta2,
        nullptr, nullptr, m2, s2, p2h, p2l, nullptr, nullptr);
    tc_hebb<2><<<gH2, 256>>>(s1bf, nullptr, H1_, H1_, p2h, p2l, hb2, mask1, beta2, d0);

    // ---- step 1 ----
    prep_ab1<<<(INP_ * H1_ + 255) / 256, 256>>>(alpha1);
    tcf<1, 2, true, false, true><<<gF, 256>>>(
        xth, xtm, nullptr, ab1h, ab1l, nullptr, INP_, d1, eta1,
        C1, nullptr, m1, s1, p1h, p1l, s1bf, s1t);
    tc_hebb<3><<<gH1, 256>>>(xh, xm, INP_, IN_, p1h, p1l, hb1, mask0, beta1, d1);
    prep_f2k<<<(H1_ * H2_ + 255) / 256, 256>>>(fc2, mask1, alpha2);
    tcf<2, 3, true, false, false><<<gF, 256>>>(
        s1t, nullptr, nullptr, f2kh, f2km, f2kl, H1_, d1, eta2,
        nullptr, nullptr, m2, s2, p2h, p2l, nullptr, nullptr);
    tc_hebb<2><<<gH2, 256>>>(s1bf, nullptr, H1_, H1_, p2h, p2l, hb2, mask1, beta2, d1);

    // ---- step 2 (final hebb updates skipped: never consumed) ----
    prep_ab1<<<(INP_ * H1_ + 255) / 256, 256>>>(alpha1);
    tcf<1, 2, false, false, true><<<gF, 256>>>(
        xth, xtm, nullptr, ab1h, ab1l, nullptr, INP_, d2, eta1,
        C1, nullptr, m1, s1, nullptr, nullptr, s1bf, s1t);
    prep_f2k<<<(H1_ * H2_ + 255) / 256, 256>>>(fc2, mask1, alpha2);
    tcf<2, 3, false, false, false><<<gF, 256>>>(
        s1t, nullptr, nullptr, f2kh, f2km, f2kl, H1_, d2, eta2,
        nullptr, nullptr, m2, s2, nullptr, nullptr, nullptr, nullptr);

    // ---- output ----
    out_gemm<<<B_ / 8, 256>>>(m2, Wm3, out);
}

// round 10
// speedup vs baseline: 2.3745x; 1.5568x over previous
#include <cuda_runtime.h>
#include <cuda_bf16.h>
#include <math.h>
#include <stdint.h>

using bf16 = __nv_bfloat16;

static constexpr int B_   = 8192;
static constexpr int IN_  = 784;
static constexpr int INP_ = 832;     // IN padded to multiple of 64
static constexpr int H1_  = 1024;
static constexpr int H2_  = 1024;
static constexpr int OUT_ = 10;

// ------------------------------ asm helpers -------------------------------
__device__ __forceinline__ uint32_t cvta_smem(const void* p) {
    uint32_t a;
    asm("{ .reg .u64 t; cvta.to.shared.u64 t, %1; cvt.u32.u64 %0, t; }"
        : "=r"(a) : "l"(p));
    return a;
}
__device__ __forceinline__ void cp16(uint32_t dst, const void* src) {
    asm volatile("cp.async.cg.shared.global [%0], [%1], 16;"
                 :: "r"(dst), "l"(src));
}
__device__ __forceinline__ void cp_commit() {
    asm volatile("cp.async.commit_group;" ::: "memory");
}
template <int N>
__device__ __forceinline__ void cp_wait() {
    asm volatile("cp.async.wait_group %0;" :: "n"(N) : "memory");
}
__device__ __forceinline__ void ldm_x4_t(uint32_t* r, uint32_t a) {
    asm volatile("ldmatrix.sync.aligned.m8n8.x4.trans.shared.b16 {%0,%1,%2,%3}, [%4];"
                 : "=r"(r[0]), "=r"(r[1]), "=r"(r[2]), "=r"(r[3]) : "r"(a));
}
__device__ __forceinline__ void mma16816(float* c, const uint32_t a[4],
                                         const uint32_t b[2]) {
    asm volatile(
        "mma.sync.aligned.m16n8k16.row.col.f32.bf16.bf16.f32 "
        "{%0,%1,%2,%3}, {%4,%5,%6,%7}, {%8,%9}, {%0,%1,%2,%3};"
        : "+f"(c[0]), "+f"(c[1]), "+f"(c[2]), "+f"(c[3])
        : "r"(a[0]), "r"(a[1]), "r"(a[2]), "r"(a[3]), "r"(b[0]), "r"(b[1]));
}

// product tables (PSET 0: 3x3 triangle; 1: single hh; 2: exact-A x 3 B)
__device__ __constant__ int c_pa[3][6] = {
    {0, 0, 1, 1, 0, 2},
    {0, 0, 0, 0, 0, 0},
    {0, 0, 0, 0, 0, 0}
};
__device__ __constant__ int c_pb[3][6] = {
    {0, 1, 0, 1, 2, 0},
    {0, 0, 0, 0, 0, 0},
    {0, 1, 2, 0, 0, 0}
};

// ------------------------------ device scratch -----------------------------
__device__ __align__(16) bf16 g_xh  [(size_t)B_ * INP_];   // natural (B, INP)
__device__ __align__(16) bf16 g_xth [(size_t)INP_ * B_];   // transposed (INP, B)
__device__ __align__(16) bf16 g_xtm [(size_t)INP_ * B_];
__device__ __align__(16) bf16 g_xtl [(size_t)INP_ * B_];
__device__ __align__(16) bf16 g_w1kh[INP_ * H1_];          // k-major (INP, H1)
__device__ __align__(16) bf16 g_w1km[INP_ * H1_];
__device__ __align__(16) bf16 g_w1kl[INP_ * H1_];
__device__ __align__(16) bf16 g_f2kh[H1_ * H2_];           // k-major (H1, H2)
__device__ __align__(16) bf16 g_f2km[H1_ * H2_];
__device__ __align__(16) bf16 g_f2kl[H1_ * H2_];
__device__ __align__(16) bf16 g_ab1h[INP_ * H1_];          // k-major (INP, H1)
__device__ __align__(16) bf16 g_s1t [(size_t)H1_ * B_];    // spikes transposed
__device__ __align__(16) bf16 g_s1bf[(size_t)B_ * H1_];    // spikes natural
__device__ __align__(16) bf16 g_p1h [(size_t)B_ * H1_];
__device__ __align__(16) bf16 g_p2h [(size_t)B_ * H2_];
__device__ float g_Wm3[H2_ * OUT_];
__device__ float g_C1 [(size_t)B_ * H1_];
__device__ float g_m1 [(size_t)B_ * H1_];
__device__ float g_s1 [(size_t)B_ * H1_];
__device__ float g_m2 [(size_t)B_ * H2_];
__device__ float g_s2 [(size_t)B_ * H2_];
__device__ float g_hb1[IN_ * H1_];
__device__ float g_hb2[H1_ * H2_];

// ------------------------------ prep kernels -------------------------------
__device__ __forceinline__ void split3(float v, bf16& h, bf16& m, bf16& l) {
    h = __float2bfloat16(v);
    float r = v - __bfloat162float(h);
    m = __float2bfloat16(r);
    l = __float2bfloat16(r - __bfloat162float(m));
}

__global__ void zero_hebb() {
    int idx = blockIdx.x * blockDim.x + threadIdx.x;
    if (idx < IN_ * H1_) g_hb1[idx] = 0.0f;
    if (idx < H1_ * H2_) g_hb2[idx] = 0.0f;
}

// natural bf16 of x (A-operand for hebb1; single product suffices — hebb
// errors enter mem attenuated ~1e5x below the fp32 noise floor)
__global__ void split_x(const float* __restrict__ x) {
    size_t idx = (size_t)blockIdx.x * blockDim.x + threadIdx.x;
    if (idx >= (size_t)B_ * INP_) return;
    int m = (int)(idx / INP_), k = (int)(idx % INP_);
    float v = (k < IN_) ? x[(size_t)m * IN_ + k] : 0.0f;
    g_xh[idx] = __float2bfloat16(v);
}

// tiled transpose + 3-split of x -> (INP, B)
__global__ void split_xt(const float* __restrict__ x) {
    __shared__ float t[32][33];
    const int kb = blockIdx.x * 32, mb = blockIdx.y * 32;
#pragma unroll
    for (int r = 0; r < 32; r += 8) {
        int m = mb + threadIdx.y + r, k = kb + threadIdx.x;
        t[threadIdx.y + r][threadIdx.x] =
            (k < IN_) ? x[(size_t)m * IN_ + k] : 0.0f;
    }
    __syncthreads();
#pragma unroll
    for (int r = 0; r < 32; r += 8) {
        int k = kb + threadIdx.y + r, m = mb + threadIdx.x;
        float v = t[threadIdx.x][threadIdx.y + r];
        size_t o = (size_t)k * B_ + m;
        split3(v, g_xth[o], g_xtm[o], g_xtl[o]);
    }
}

// W1 masked, k-major 3-split
__global__ void prep_w1k(const float* __restrict__ fc1, const float* __restrict__ mask0) {
    int idx = blockIdx.x * blockDim.x + threadIdx.x;
    if (idx >= INP_ * H1_) return;
    int k = idx / H1_, n = idx % H1_;
    float v = (k < IN_) ? fc1[n * IN_ + k] * mask0[k * H1_ + n] : 0.0f;
    split3(v, g_w1kh[idx], g_w1km[idx], g_w1kl[idx]);
}

// fw2 = W2m + alpha2*hb2, k-major 3-split
__global__ void prep_f2k(const float* __restrict__ fc2, const float* __restrict__ mask1,
                         const float* __restrict__ alpha2) {
    int idx = blockIdx.x * blockDim.x + threadIdx.x;
    if (idx >= H1_ * H2_) return;
    int k = idx / H2_, n = idx % H2_;
    float v = fmaf(alpha2[0], g_hb2[idx], fc2[n * H1_ + k] * mask1[idx]);
    split3(v, g_f2kh[idx], g_f2km[idx], g_f2kl[idx]);
}

// ab1 = alpha1*hb1, k-major single bf16 (term enters mem at ~5e-3 scale;
// 1-split rounding ~4e-7 absolute in mem, below fp32 floor)
__global__ void prep_ab1(const float* __restrict__ alpha1) {
    int idx = blockIdx.x * blockDim.x + threadIdx.x;
    if (idx >= INP_ * H1_) return;
    int k = idx / H1_, n = idx % H1_;
    float v = (k < IN_) ? alpha1[0] * g_hb1[k * H1_ + n] : 0.0f;
    g_ab1h[idx] = __float2bfloat16(v);
}

__global__ void prep_w3(const float* __restrict__ fc3, const float* __restrict__ mask2) {
    int idx = blockIdx.x * blockDim.x + threadIdx.x;
    if (idx >= H2_ * OUT_) return;
    int k = idx / OUT_, n = idx - k * OUT_;
    g_Wm3[idx] = fc3[n * H2_ + k] * mask2[idx];
}

// ---------------------------------------------------------------------------
// Forward HMMA GEMM, trans-ldmatrix path (round-9 proven), TWO-LEVEL
// ACCUMULATION (promotion every 32-k chunk), now 3-stage cp.async pipeline.
// CTA tile 128x64, warps 4x2 (m32 x n32 each).
// EP 1: st = acc (C1out = acc); EP 2: st = d*(C1in + acc); EP 3: st = d*acc
// ---------------------------------------------------------------------------
template <int PSET, int EP, bool POST, bool FIRST, bool SPKT>
__global__ void __launch_bounds__(256, 2)
tcf(const bf16* __restrict__ A0, const bf16* __restrict__ A1,
    const bf16* __restrict__ A2,
    const bf16* __restrict__ B0, const bf16* __restrict__ B1,
    const bf16* __restrict__ B2,
    int Kpad, float dscale, const float* __restrict__ eta,
    const float* __restrict__ C1in, float* __restrict__ C1out,
    float* __restrict__ memA, float* __restrict__ spkA,
    bf16* __restrict__ postH, bf16* __restrict__ spkBf,
    bf16* __restrict__ spkT) {
    constexpr int NP = (PSET == 0) ? 6 : (PSET == 1) ? 1 : 3;
    __shared__ __align__(16) bf16 sA[3][32 * 136];
    __shared__ __align__(16) bf16 sB[3][32 * 72];

    const int tid = threadIdx.x, lane = tid & 31, wid = tid >> 5;
    const int wm = wid & 3, wn = wid >> 2;        // 4 x 2 warps (m32 x n32)
    const int bn = blockIdx.x, bm = blockIdx.y;
    const int KC = Kpad >> 5;
    const int V = NP * KC;

    const bf16* Ap[3] = {A0, A1, A2};
    const bf16* Bp[3] = {B0, B1, B2};

    const uint32_t aB0 = cvta_smem(&sA[0][0]);
    const uint32_t bB0 = cvta_smem(&sB[0][0]);
    constexpr uint32_t STGA = 32 * 136 * 2;
    constexpr uint32_t STGB = 32 * 72 * 2;

    const int lr = tid >> 3;          // 0..31 (k row within chunk)
    const int lc = tid & 7;           // col group

    float acc[2][4][4];               // mma accumulator (short RZ chains)
    float accM[2][4][4];              // promoted IEEE fp32 accumulator
#pragma unroll
    for (int i = 0; i < 2; ++i)
#pragma unroll
        for (int j = 0; j < 4; ++j)
#pragma unroll
            for (int q = 0; q < 4; ++q) { acc[i][j][q] = 0.0f; accM[i][j][q] = 0.0f; }

    auto issue = [&](int v, int s) {
        int p = v / KC, c = v - p * KC;
        const bf16* ag = Ap[c_pa[PSET][p]] + (size_t)(c * 32 + lr) * B_ + bm * 128 + lc * 16;
        const bf16* bg = Bp[c_pb[PSET][p]] + (size_t)(c * 32 + lr) * 1024 + bn * 64 + lc * 8;
        uint32_t offA = (uint32_t)(lr * 136 + lc * 16) * 2 + (uint32_t)s * STGA;
        uint32_t offB = (uint32_t)(lr * 72 + lc * 8) * 2 + (uint32_t)s * STGB;
        cp16(aB0 + offA, ag);
        cp16(aB0 + offA + 16, ag + 8);
        cp16(bB0 + offB, bg);
        cp_commit();
    };

    issue(0, 0);
    issue(1, 1);
    issue(2, 2);
    int s = 0;
    for (int v = 0; v < V; ++v) {
        if (v + 3 <= V) cp_wait<2>();
        else if (v + 2 == V) cp_wait<1>();
        else cp_wait<0>();
        __syncthreads();
        const uint32_t aB = aB0 + (uint32_t)s * STGA;
        const uint32_t bB = bB0 + (uint32_t)s * STGB;
#pragma unroll
        for (int kk = 0; kk < 2; ++kk) {
            uint32_t af[2][4];
#pragma unroll
            for (int i = 0; i < 2; ++i) {
                int krow = kk * 16 + ((lane >> 4) & 1) * 8 + (lane & 7);
                int mcol = wm * 32 + i * 16 + ((lane >> 3) & 1) * 8;
                ldm_x4_t(af[i], aB + (uint32_t)(krow * 136 + mcol) * 2);
            }
            uint32_t bf_[4][2];
#pragma unroll
            for (int jj = 0; jj < 2; ++jj) {
                uint32_t r[4];
                int krow = kk * 16 + ((lane >> 3) & 1) * 8 + (lane & 7);
                int ncol = wn * 32 + jj * 16 + ((lane >> 4) & 1) * 8;
                ldm_x4_t(r, bB + (uint32_t)(krow * 72 + ncol) * 2);
                bf_[jj * 2][0] = r[0]; bf_[jj * 2][1] = r[1];
                bf_[jj * 2 + 1][0] = r[2]; bf_[jj * 2 + 1][1] = r[3];
            }
#pragma unroll
            for (int i = 0; i < 2; ++i)
#pragma unroll
                for (int j = 0; j < 4; ++j)
                    mma16816(acc[i][j], af[i], bf_[j]);
        }
        // ---- promotion: IEEE fp32 add, reset mma accumulator ----
#pragma unroll
        for (int i = 0; i < 2; ++i)
#pragma unroll
            for (int j = 0; j < 4; ++j)
#pragma unroll
                for (int q = 0; q < 4; ++q) {
                    accM[i][j][q] += acc[i][j][q];
                    acc[i][j][q] = 0.0f;
                }
        __syncthreads();
        if (v + 3 < V) issue(v + 3, s);
        s = (s == 2) ? 0 : s + 1;
    }

    // -------- fused SNN epilogue (proven mapping + proven math) --------
    const int mbase = bm * 128 + wm * 32;
    const int nbase = bn * 64 + wn * 32;
#pragma unroll
    for (int i = 0; i < 2; ++i) {
#pragma unroll
        for (int h = 0; h < 2; ++h) {
            const int m = mbase + i * 16 + (lane >> 2) + h * 8;
            const size_t roff = (size_t)m * 1024;
#pragma unroll
            for (int j = 0; j < 4; ++j) {
                const int n = nbase + j * 8 + (lane & 3) * 2;
                const size_t idx = roff + n;
                float c0 = accM[i][j][h * 2 + 0];
                float c1 = accM[i][j][h * 2 + 1];
                float st0, st1;
                if (EP == 1) { st0 = c0; st1 = c1; }
                else if (EP == 2) {
                    float2 cv = *reinterpret_cast<const float2*>(C1in + idx);
                    st0 = dscale * (cv.x + c0);
                    st1 = dscale * (cv.y + c1);
                } else { st0 = dscale * c0; st1 = dscale * c1; }
                float m0v, m1v;
                if (FIRST) { m0v = st0; m1v = st1; }
                else {
                    float2 mv = *reinterpret_cast<const float2*>(memA + idx);
                    float2 sv = *reinterpret_cast<const float2*>(spkA + idx);
                    m0v = (mv.x - sv.x * 0.5f) * 0.8f + st0;
                    m1v = (mv.y - sv.y * 0.5f) * 0.8f + st1;
                }
                float sp0 = ((m0v - 0.5f) > 0.0f) ? 1.0f : 0.0f;
                float sp1 = ((m1v - 0.5f) > 0.0f) ? 1.0f : 0.0f;
                *reinterpret_cast<float2*>(memA + idx) = make_float2(m0v, m1v);
                *reinterpret_cast<float2*>(spkA + idx) = make_float2(sp0, sp1);
                if (EP == 1)
                    *reinterpret_cast<float2*>(C1out + idx) = make_float2(c0, c1);
                if (POST) {
                    float2 ev = *reinterpret_cast<const float2*>(eta + n);
                    float p0 = tanhf(2.0f * m0v - ev.x);
                    float p1 = tanhf(2.0f * m1v - ev.y);
                    __nv_bfloat162 hv;
                    hv.x = __float2bfloat16(p0);
                    hv.y = __float2bfloat16(p1);
                    *reinterpret_cast<__nv_bfloat162*>(postH + idx) = hv;
                }
                if (SPKT) {
                    __nv_bfloat162 sv2;
                    sv2.x = __float2bfloat16(sp0);
                    sv2.y = __float2bfloat16(sp1);
                    *reinterpret_cast<__nv_bfloat162*>(spkBf + idx) = sv2;
                    spkT[(size_t)n * B_ + m]       = sv2.x;
                    spkT[(size_t)(n + 1) * B_ + m] = sv2.y;
                }
            }
        }
    }
}

// ---------------------------------------------------------------------------
// Hebb HMMA GEMM (round-7 proven structure), single product (hebb error is
// attenuated ~1e5x before entering mem), 3-stage cp.async pipeline.
// Hb(M x 1024) = 0.8*Hb + (1-mask)*beta[m]*(d/8192)*(A^T @ P)
// ---------------------------------------------------------------------------
__global__ void __launch_bounds__(256)
tc_hebb(const bf16* __restrict__ A, int Mpitch, int M,
        const bf16* __restrict__ P,
        float* __restrict__ Hb, const float* __restrict__ mask,
        const float* __restrict__ beta, float dscale) {
    __shared__ __align__(16) bf16 sA[3][32 * 72];
    __shared__ __align__(16) bf16 sP[3][32 * 72];
    const int tid = threadIdx.x, lane = tid & 31, wid = tid >> 5;
    const int wm = wid & 3, wn = wid >> 2;
    const int m0b = blockIdx.y * 64, n0b = blockIdx.x * 64;
    const uint32_t aB0 = cvta_smem(&sA[0][0]);
    const uint32_t pB0 = cvta_smem(&sP[0][0]);
    constexpr uint32_t STG = 32 * 72 * 2;

    const int srow = tid >> 3, sc = tid & 7;

    float acc[4][4];
#pragma unroll
    for (int j = 0; j < 4; ++j)
#pragma unroll
        for (int q = 0; q < 4; ++q) acc[j][q] = 0.0f;

    constexpr int V = 8192 / 32;

    auto issue = [&](int c, int s) {
        const bf16* ag = A + (size_t)(c * 32 + srow) * Mpitch + m0b + sc * 8;
        const bf16* pg = P + (size_t)(c * 32 + srow) * 1024 + n0b + sc * 8;
        uint32_t off = (uint32_t)(srow * 72 + sc * 8) * 2 + (uint32_t)s * STG;
        cp16(aB0 + off, ag);
        cp16(pB0 + off, pg);
        cp_commit();
    };

    issue(0, 0);
    issue(1, 1);
    issue(2, 2);
    int s = 0;
    for (int v = 0; v < V; ++v) {
        if (v + 3 <= V) cp_wait<2>();
        else if (v + 2 == V) cp_wait<1>();
        else cp_wait<0>();
        __syncthreads();
        const uint32_t aB = aB0 + (uint32_t)s * STG;
        const uint32_t pB = pB0 + (uint32_t)s * STG;
#pragma unroll
        for (int kk = 0; kk < 2; ++kk) {
            uint32_t af[4];
            {
                int krow = kk * 16 + ((lane >> 4) & 1) * 8 + (lane & 7);
                int mcol = wm * 16 + ((lane >> 3) & 1) * 8;
                ldm_x4_t(af, aB + (uint32_t)(krow * 72 + mcol) * 2);
            }
            uint32_t bf_[4][2];
#pragma unroll
            for (int jj = 0; jj < 2; ++jj) {
                uint32_t r[4];
                int krow = kk * 16 + ((lane >> 3) & 1) * 8 + (lane & 7);
                int ncol = wn * 32 + jj * 16 + ((lane >> 4) & 1) * 8;
                ldm_x4_t(r, pB + (uint32_t)(krow * 72 + ncol) * 2);
                bf_[jj * 2][0] = r[0]; bf_[jj * 2][1] = r[1];
                bf_[jj * 2 + 1][0] = r[2]; bf_[jj * 2 + 1][1] = r[3];
            }
#pragma unroll
            for (int j = 0; j < 4; ++j)
                mma16816(acc[j], af, bf_[j]);
        }
        __syncthreads();
        if (v + 3 < V) issue(v + 3, s);
        s = (s == 2) ? 0 : s + 1;
    }

    const float inv = dscale * (1.0f / 8192.0f);
#pragma unroll
    for (int h = 0; h < 2; ++h) {
        const int m = m0b + wm * 16 + (lane >> 2) + h * 8;
        if (m < M) {
            const float bs = beta[m] * inv;
            const size_t roff = (size_t)m * 1024;
#pragma unroll
            for (int j = 0; j < 4; ++j) {
                const int n = n0b + wn * 32 + j * 8 + (lane & 3) * 2;
                const size_t idx = roff + n;
                float2 hb = *reinterpret_cast<const float2*>(Hb + idx);
                float2 mk = *reinterpret_cast<const float2*>(mask + idx);
                hb.x = 0.8f * hb.x + (1.0f - mk.x) * bs * acc[j][h * 2 + 0];
                hb.y = 0.8f * hb.y + (1.0f - mk.y) * bs * acc[j][h * 2 + 1];
                *reinterpret_cast<float2*>(Hb + idx) = hb;
            }
        }
    }
}

// ---------------------------------------------------------------------------
// Output GEMM: out(8192 x 10) = m2 @ Wm3   (fp32 SIMT, proven)
// ---------------------------------------------------------------------------
__global__ void __launch_bounds__(256)
out_gemm(const float* __restrict__ m2, const float* __restrict__ Wm3,
         float* __restrict__ out) {
    __shared__ float sW[H2_ * OUT_];
    const int tid = threadIdx.x;
    for (int i = tid; i < H2_ * OUT_; i += blockDim.x) sW[i] = Wm3[i];
    __syncthreads();

    const int warp = tid >> 5, lane = tid & 31;
    const int b = blockIdx.x * 8 + warp;
    const float* row = m2 + (size_t)b * H2_;

    float acc[OUT_];
#pragma unroll
    for (int j = 0; j < OUT_; j++) acc[j] = 0.0f;
    for (int k = lane; k < H2_; k += 32) {
        float v = row[k];
#pragma unroll
        for (int j = 0; j < OUT_; j++) acc[j] = fmaf(v, sW[k * OUT_ + j], acc[j]);
    }
#pragma unroll
    for (int j = 0; j < OUT_; j++) {
        float sv = acc[j];
#pragma unroll
        for (int o = 16; o > 0; o >>= 1) sv += __shfl_xor_sync(0xffffffffu, sv, o);
        if (lane == 0) out[(size_t)b * OUT_ + j] = sv;
    }
}

// ---------------------------------------------------------------------------
extern "C" void kernel_launch(void* const* d_in, const int* in_sizes, int n_in,
                              void* d_out, int out_size) {
    const float* x      = (const float*)d_in[0];
    const float* mask0  = (const float*)d_in[1];
    const float* mask1  = (const float*)d_in[2];
    const float* mask2  = (const float*)d_in[3];
    const float* fc1    = (const float*)d_in[4];
    const float* fc2    = (const float*)d_in[5];
    const float* fc3    = (const float*)d_in[6];
    const float* alpha1 = (const float*)d_in[7];
    const float* alpha2 = (const float*)d_in[8];
    const float* beta1  = (const float*)d_in[9];
    const float* beta2  = (const float*)d_in[10];
    const float* eta1   = (const float*)d_in[11];
    const float* eta2   = (const float*)d_in[12];
    float* out = (float*)d_out;

    bf16 *xh, *xth, *xtm, *xtl, *w1kh, *w1km, *w1kl;
    bf16 *f2kh, *f2km, *f2kl, *ab1h, *s1t, *s1bf, *p1h, *p2h;
    float *Wm3, *C1, *m1, *s1, *m2, *s2, *hb1, *hb2;
    cudaGetSymbolAddress((void**)&xh,   g_xh);
    cudaGetSymbolAddress((void**)&xth,  g_xth);
    cudaGetSymbolAddress((void**)&xtm,  g_xtm);
    cudaGetSymbolAddress((void**)&xtl,  g_xtl);
    cudaGetSymbolAddress((void**)&w1kh, g_w1kh);
    cudaGetSymbolAddress((void**)&w1km, g_w1km);
    cudaGetSymbolAddress((void**)&w1kl, g_w1kl);
    cudaGetSymbolAddress((void**)&f2kh, g_f2kh);
    cudaGetSymbolAddress((void**)&f2km, g_f2km);
    cudaGetSymbolAddress((void**)&f2kl, g_f2kl);
    cudaGetSymbolAddress((void**)&ab1h, g_ab1h);
    cudaGetSymbolAddress((void**)&s1t,  g_s1t);
    cudaGetSymbolAddress((void**)&s1bf, g_s1bf);
    cudaGetSymbolAddress((void**)&p1h,  g_p1h);
    cudaGetSymbolAddress((void**)&p2h,  g_p2h);
    cudaGetSymbolAddress((void**)&Wm3,  g_Wm3);
    cudaGetSymbolAddress((void**)&C1,   g_C1);
    cudaGetSymbolAddress((void**)&m1,   g_m1);
    cudaGetSymbolAddress((void**)&s1,   g_s1);
    cudaGetSymbolAddress((void**)&m2,   g_m2);
    cudaGetSymbolAddress((void**)&s2,   g_s2);
    cudaGetSymbolAddress((void**)&hb1,  g_hb1);
    cudaGetSymbolAddress((void**)&hb2,  g_hb2);

    const float d0 = 1.0f;
    const float d1 = 0.98019867330675525f;   // float32(exp(-1/50))
    const float d2 = 0.96078943915232320f;   // float32(exp(-2/50))

    // ---- prep ----
    zero_hebb<<<(H1_ * H2_ + 255) / 256, 256>>>();
    split_x<<<(int)(((size_t)B_ * INP_ + 255) / 256), 256>>>(x);
    split_xt<<<dim3(INP_ / 32, B_ / 32), dim3(32, 8)>>>(x);
    prep_w1k<<<(INP_ * H1_ + 255) / 256, 256>>>(fc1, mask0);
    prep_w3<<<(H2_ * OUT_ + 255) / 256, 256>>>(fc3, mask2);
    prep_f2k<<<(H1_ * H2_ + 255) / 256, 256>>>(fc2, mask1, alpha2);  // hb2 == 0

    dim3 gF(16, 64);       // forward 128x64 tiles over (8192, 1024)
    dim3 gH1(16, 13);      // hebb1 64x64 tiles over (784, 1024)
    dim3 gH2(16, 16);      // hebb2 over (1024, 1024)

    // ---- step 0 ----
    tcf<0, 1, true, true, true><<<gF, 256>>>(
        xth, xtm, xtl, w1kh, w1km, w1kl, INP_, d0, eta1,
        nullptr, C1, m1, s1, p1h, s1bf, s1t);
    tc_hebb<<<gH1, 256>>>(xh, INP_, IN_, p1h, hb1, mask0, beta1, d0);
    tcf<2, 3, true, true, false><<<gF, 256>>>(
        s1t, nullptr, nullptr, f2kh, f2km, f2kl, H1_, d0, eta2,
        nullptr, nullptr, m2, s2, p2h, nullptr, nullptr);
    tc_hebb<<<gH2, 256>>>(s1bf, H1_, H1_, p2h, hb2, mask1, beta2, d0);

    // ---- step 1 ----
    prep_ab1<<<(INP_ * H1_ + 255) / 256, 256>>>(alpha1);
    tcf<1, 2, true, false, true><<<gF, 256>>>(
        xth, nullptr, nullptr, ab1h, nullptr, nullptr, INP_, d1, eta1,
        C1, nullptr, m1, s1, p1h, s1bf, s1t);
    tc_hebb<<<gH1, 256>>>(xh, INP_, IN_, p1h, hb1, mask0, beta1, d1);
    prep_f2k<<<(H1_ * H2_ + 255) / 256, 256>>>(fc2, mask1, alpha2);
    tcf<2, 3, true, false, false><<<gF, 256>>>(
        s1t, nullptr, nullptr, f2kh, f2km, f2kl, H1_, d1, eta2,
        nullptr, nullptr, m2, s2, p2h, nullptr, nullptr);
    tc_hebb<<<gH2, 256>>>(s1bf, H1_, H1_, p2h, hb2, mask1, beta2, d1);

    // ---- step 2 (final hebb updates skipped: never consumed) ----
    prep_ab1<<<(INP_ * H1_ + 255) / 256, 256>>>(alpha1);
    tcf<1, 2, false, false, true><<<gF, 256>>>(
        xth, nullptr, nullptr, ab1h, nullptr, nullptr, INP_, d2, eta1,
        C1, nullptr, m1, s1, nullptr, s1bf, s1t);
    prep_f2k<<<(H1_ * H2_ + 255) / 256, 256>>>(fc2, mask1, alpha2);
    tcf<2, 3, false, false, false><<<gF, 256>>>(
        s1t, nullptr, nullptr, f2kh, f2km, f2kl, H1_, d2, eta2,
        nullptr, nullptr, m2, s2, nullptr, nullptr, nullptr);

    // ---- output ----
    out_gemm<<<B_ / 8, 256>>>(m2, Wm3, out);
}